// round 12
// baseline (speedup 1.0000x reference)
#include <cuda_runtime.h>
#include <cuda_fp16.h>
#include <cstdint>

#define B_      1024
#define K_      11
#define L_KIN_  128
#define L_SUB_  64
#define L_STR_  128
#define D_SEQ_  1280
#define D_STR_  512
#define EMB_    1792
#define EMB2_   2564
#define M_      (B_ * K_)
#define NCHUNK_ 44
#define KP1     1792
#define KP2     2624
#define NP_R21  2816

#define GBM 128
#define GBN 128
#define GSTAGES 3
#define HS 72
#define GA_BUF (GBM * HS)
#define GB_BUF (GBN * HS)
#define GSMEM_BYTES (GSTAGES * (GA_BUF + GB_BUF) * 2)   // 110592

__device__ float  g_X [(size_t)M_ * EMB_];
__device__ __half g_Y [(size_t)M_ * KP2];
__device__ __half g_XA[(size_t)M_ * KP1];
__device__ __half g_XB[(size_t)M_ * KP1];
__device__ __half g_KA[(size_t)B_ * D_SEQ_];
__device__ __half g_KB[(size_t)B_ * D_SEQ_];
__device__ float  g_P1[(size_t)M_ * D_SEQ_];
__device__ float  g_P2[(size_t)M_ * D_SEQ_];
__device__ __half g_Wt[21905408];
__device__ float  g_kin[(size_t)B_ * D_SEQ_];
__device__ float  g_Qg[(size_t)B_ * D_SEQ_];
__device__ float  g_Qr[(size_t)B_ * EMB2_];
__device__ float  g_Tg[21 * D_SEQ_];
__device__ float  g_Tr[21 * EMB2_];
__device__ int    g_cnt[21];
__device__ float  g_psum [NCHUNK_ * EMB_];
__device__ float  g_psq  [NCHUNK_ * EMB_];
__device__ float  g_psumK[4 * D_SEQ_];
__device__ float  g_psqK [4 * D_SEQ_];
__device__ float  g_ss  [8 * EMB2_];

__constant__ float c_props[21 * 4] = {
    0,0,0,0,  1,0,0,0,  0,0,0,0,  0,0,0,0,  1,0,0,0,  0,0,0,0,  0,0,0,0,
    1,0,0,0,  1,0,0,0,  0,0,0,0,  0,0,1,0,  0,0,0,0,  0,0,0,1,  0,0,1,0,
    1,0,0,0,  0,0,0,1,  0,1,0,0,  0,0,0,1,  0,1,0,0,  0,1,0,0,  0,0,0,0
};

__device__ __forceinline__ float sigmoidf_(float x) { return 1.f / (1.f + expf(-x)); }

__device__ __forceinline__ void mma_f16(float* d, const unsigned* a, const unsigned* b) {
    asm volatile(
        "mma.sync.aligned.m16n8k16.row.col.f32.f16.f16.f32 "
        "{%0,%1,%2,%3}, {%4,%5,%6,%7}, {%8,%9}, {%0,%1,%2,%3};\n"
        : "+f"(d[0]), "+f"(d[1]), "+f"(d[2]), "+f"(d[3])
        : "r"(a[0]), "r"(a[1]), "r"(a[2]), "r"(a[3]), "r"(b[0]), "r"(b[1]));
}
__device__ __forceinline__ void cp16u(unsigned dst, const void* src) {
    asm volatile("cp.async.cg.shared.global [%0], [%1], 16;\n" :: "r"(dst), "l"(src));
}
__device__ __forceinline__ void ldm4(unsigned& r0, unsigned& r1, unsigned& r2, unsigned& r3,
                                     unsigned addr) {
    asm volatile("ldmatrix.sync.aligned.m8n8.x4.shared.b16 {%0,%1,%2,%3}, [%4];"
                 : "=r"(r0), "=r"(r1), "=r"(r2), "=r"(r3) : "r"(addr));
}

// ---- prep: weight transpose (blocks 0..21391) + kin-mean/build-gfeat (rest) ----
__global__ __launch_bounds__(256) void prep_kernel(
    const float* __restrict__ W0, const float* __restrict__ W1, const float* __restrict__ W2,
    const float* __restrict__ W3, const float* __restrict__ W4, const float* __restrict__ W5,
    __half* __restrict__ D0, __half* __restrict__ D1, __half* __restrict__ D2,
    __half* __restrict__ D3, __half* __restrict__ D4, __half* __restrict__ D5,
    const float* __restrict__ kin_in, const float* __restrict__ sub,
    const float* __restrict__ n2, const float* __restrict__ phos,
    const int* __restrict__ position,
    float* __restrict__ kin_out, float* __restrict__ X, float* __restrict__ node_feature) {
    __shared__ float t[32][33];
    int bx = blockIdx.x;
    if (bx < 21392) {
        const float* W; __half* D; int K, N, KP, kb, blk;
        if      (bx < 2240)  { W=W0; D=D0; K=EMB_;  N=1280;  KP=KP1; kb=56; blk=bx; }
        else if (bx < 5376)  { W=W1; D=D1; K=EMB_;  N=1792;  KP=KP1; kb=56; blk=bx-2240; }
        else if (bx < 7616)  { W=W2; D=D2; K=EMB_;  N=1280;  KP=KP1; kb=56; blk=bx-5376; }
        else if (bx < 10896) { W=W3; D=D3; K=EMB2_; N=1280;  KP=KP2; kb=82; blk=bx-7616; }
        else if (bx < 18112) { W=W4; D=D4; K=EMB2_; N=EMB2_; KP=KP2; kb=82; blk=bx-10896; }
        else                 { W=W5; D=D5; K=EMB2_; N=1280;  KP=KP2; kb=82; blk=bx-18112; }
        int k0 = (blk % kb) * 32, n0 = (blk / kb) * 32;
        int tx = threadIdx.x & 31, ty = threadIdx.x >> 5;
        #pragma unroll
        for (int j = 0; j < 4; ++j) {
            int k = k0 + ty + j * 8, n = n0 + tx;
            t[ty + j * 8][tx] = (k < K && n < N) ? W[(size_t)k * N + n] : 0.f;
        }
        __syncthreads();
        #pragma unroll
        for (int j = 0; j < 4; ++j) {
            int n = n0 + ty + j * 8, k = k0 + tx;
            D[(size_t)n * KP + k] = __float2half(t[tx][ty + j * 8]);
        }
        return;
    }
    int bx2 = bx - 21392;
    int b = bx2 / (K_ + 1), k = bx2 % (K_ + 1);
    if (k == K_) {
        const float* base = kin_in + ((size_t)b * L_KIN_ + 1) * D_SEQ_;
        for (int i = threadIdx.x; i < D_SEQ_ / 4; i += blockDim.x) {
            float4 acc = make_float4(0.f, 0.f, 0.f, 0.f);
            #pragma unroll 4
            for (int r = 0; r < L_KIN_ - 1; ++r) {
                float4 v = *(const float4*)(base + (size_t)r * D_SEQ_ + i * 4);
                acc.x += v.x; acc.y += v.y; acc.z += v.z; acc.w += v.w;
            }
            const float inv = 1.f / 127.f;
            *(float4*)(kin_out + (size_t)b * D_SEQ_ + i * 4) =
                make_float4(acc.x * inv, acc.y * inv, acc.z * inv, acc.w * inv);
        }
        return;
    }
    size_t m = (size_t)b * K_ + k;
    const float* src1 = sub + ((size_t)b * L_SUB_ + 1 + k) * D_SEQ_;
    float* dst = X + m * EMB_;
    float* nf  = node_feature + m * D_SEQ_;
    bool mid = (k == K_ / 2);
    for (int i = threadIdx.x; i < D_SEQ_ / 4; i += blockDim.x) {
        float4 v = *(const float4*)(src1 + i * 4);
        *(float4*)(nf + i * 4) = v;
        if (mid) {
            float4 p = *(const float4*)(phos + i * 4);
            v.x += p.x; v.y += p.y; v.z += p.z; v.w += p.w;
        }
        *(float4*)(dst + i * 4) = v;
    }
    int row = position[b] + k - K_ / 2;
    bool ok = (row >= 0 && row < L_STR_);
    const float* src2 = n2 + ((size_t)b * L_STR_ + (ok ? row : 0)) * D_STR_;
    for (int i = threadIdx.x; i < D_STR_ / 4; i += blockDim.x) {
        float4 v = make_float4(0.f, 0.f, 0.f, 0.f);
        if (ok) v = *(const float4*)(src2 + i * 4);
        if (mid) {
            float4 p = *(const float4*)(phos + D_SEQ_ + i * 4);
            v.x += p.x; v.y += p.y; v.z += p.z; v.w += p.w;
        }
        *(float4*)(dst + D_SEQ_ + i * 4) = v;
    }
}

__global__ __launch_bounds__(256) void colstats_partial(
    const float* __restrict__ X, float* __restrict__ psum, float* __restrict__ psq,
    int ncols, int rows_per_chunk) {
    int col = blockIdx.x * blockDim.x + threadIdx.x;
    if (col >= ncols) return;
    int r0 = blockIdx.y * rows_per_chunk;
    float s = 0.f, q = 0.f;
    const float* p = X + (size_t)r0 * ncols + col;
    #pragma unroll 4
    for (int r = 0; r < rows_per_chunk; ++r, p += ncols) {
        float v = *p;
        s += v; q += v * v;
    }
    psum[blockIdx.y * ncols + col] = s;
    psq [blockIdx.y * ncols + col] = q;
}

__global__ __launch_bounds__(256) void finalize_stats(
    const float* __restrict__ psum, const float* __restrict__ psq, int ncols,
    const float* __restrict__ gA, const float* __restrict__ bA,
    const float* __restrict__ gB, const float* __restrict__ bB,
    float* __restrict__ sA, float* __restrict__ tA,
    float* __restrict__ sB, float* __restrict__ tB) {
    int col = blockIdx.x * blockDim.x + threadIdx.x;
    if (col >= ncols) return;
    float s = 0.f, q = 0.f;
    for (int c = 0; c < NCHUNK_; ++c) {
        s += psum[c * ncols + col];
        q += psq [c * ncols + col];
    }
    const float inv_n = 1.f / (float)M_;
    float mean = s * inv_n;
    float var  = q * inv_n - mean * mean;
    float inv  = rsqrtf(var + 1e-5f);
    float sa = gA[col] * inv; sA[col] = sa; tA[col] = bA[col] - mean * sa;
    float sb = gB[col] * inv; sB[col] = sb; tB[col] = bB[col] - mean * sb;
}

// ---- merged stage-2 stats: X2 chunks (0..219), kin chunks (220..239), hist (240) ----
__global__ __launch_bounds__(256) void stats2_kernel(
    const float* __restrict__ X2, const float* __restrict__ kin, const int* __restrict__ seq,
    float* __restrict__ psum, float* __restrict__ psq,
    float* __restrict__ psumK, float* __restrict__ psqK, int* __restrict__ cnt) {
    int bx = blockIdx.x;
    if (bx < 220) {
        int col = (bx % 5) * 256 + threadIdx.x;
        int chunk = bx / 5;
        float s = 0.f, q = 0.f;
        const float* p = X2 + (size_t)chunk * 256 * D_SEQ_ + col;
        #pragma unroll 4
        for (int r = 0; r < 256; ++r, p += D_SEQ_) { float v = *p; s += v; q += v * v; }
        psum[chunk * D_SEQ_ + col] = s;
        psq [chunk * D_SEQ_ + col] = q;
    } else if (bx < 240) {
        int b2 = bx - 220;
        int col = (b2 % 5) * 256 + threadIdx.x;
        int chunk = b2 / 5;
        float s = 0.f, q = 0.f;
        const float* p = kin + (size_t)chunk * 256 * D_SEQ_ + col;
        #pragma unroll 4
        for (int r = 0; r < 256; ++r, p += D_SEQ_) { float v = *p; s += v; q += v * v; }
        psumK[chunk * D_SEQ_ + col] = s;
        psqK [chunk * D_SEQ_ + col] = q;
    } else {
        __shared__ int h[21];
        if (threadIdx.x < 21) h[threadIdx.x] = 0;
        __syncthreads();
        for (int i = threadIdx.x; i < M_; i += blockDim.x) atomicAdd(&h[seq[i]], 1);
        __syncthreads();
        if (threadIdx.x < 21) cnt[threadIdx.x] = h[threadIdx.x];
    }
}

__global__ __launch_bounds__(256) void finalize_stats2(
    const float* __restrict__ psum, const float* __restrict__ psq,
    const float* __restrict__ psumK, const float* __restrict__ psqK,
    const int* __restrict__ cnt,
    const float* __restrict__ gA, const float* __restrict__ bA,
    const float* __restrict__ gB, const float* __restrict__ bB,
    float* __restrict__ sA, float* __restrict__ tA,
    float* __restrict__ sB, float* __restrict__ tB) {
    int col = blockIdx.x * blockDim.x + threadIdx.x;
    if (col >= EMB2_) return;
    float mean, var;
    if (col < D_SEQ_) {
        float s = 0.f, q = 0.f;
        for (int c = 0; c < NCHUNK_; ++c) { s += psum[c * D_SEQ_ + col]; q += psq[c * D_SEQ_ + col]; }
        mean = s / (float)M_; var = q / (float)M_ - mean * mean;
    } else if (col < 2 * D_SEQ_) {
        int j = col - D_SEQ_;
        float s = 0.f, q = 0.f;
        for (int c = 0; c < 4; ++c) { s += psumK[c * D_SEQ_ + j]; q += psqK[c * D_SEQ_ + j]; }
        mean = s / (float)B_; var = q / (float)B_ - mean * mean;
    } else {
        int j = col - 2 * D_SEQ_;
        float s = 0.f;
        for (int sd = 0; sd < 21; ++sd) s += (float)cnt[sd] * c_props[sd * 4 + j];
        mean = s / (float)M_; var = mean - mean * mean;
    }
    float inv = rsqrtf(var + 1e-5f);
    float sa = gA[col] * inv; sA[col] = sa; tA[col] = bA[col] - mean * sa;
    float sb = gB[col] * inv; sB[col] = sb; tB[col] = bB[col] - mean * sb;
}

__global__ __launch_bounds__(256) void props_merged(
    const float* __restrict__ Wg, const float* __restrict__ Wr,
    const float* __restrict__ sg, const float* __restrict__ tg,
    const float* __restrict__ sr, const float* __restrict__ tr,
    float* __restrict__ Tg, float* __restrict__ Tr) {
    int idx = blockIdx.x * blockDim.x + threadIdx.x;
    const float* W; const float* s; const float* t; float* T; int N; int i;
    if (idx < 21 * 1280) { W = Wg; s = sg; t = tg; T = Tg; N = 1280; i = idx; }
    else {
        i = idx - 21 * 1280;
        if (i >= 21 * EMB2_) return;
        W = Wr; s = sr; t = tr; T = Tr; N = EMB2_;
    }
    int sid = i / N, n = i % N;
    float acc = 0.f;
    #pragma unroll
    for (int j = 0; j < 4; ++j) {
        float pv = fmaxf(fmaf(c_props[sid * 4 + j], s[j], t[j]), 0.f);
        acc += pv * W[(size_t)(2 * D_SEQ_ + j) * N + n];
    }
    T[i] = acc;
}

__global__ __launch_bounds__(256) void bn_transform_kernel(
    const float* __restrict__ X,
    const float* __restrict__ s1, const float* __restrict__ t1,
    const float* __restrict__ s2, const float* __restrict__ t2,
    __half* __restrict__ XA, __half* __restrict__ XB, int ncols, int ldo, int nj) {
    int j = blockIdx.x * blockDim.x + threadIdx.x;
    if (j >= nj) return;
    int row = blockIdx.y;
    int c = j * 2;
    const float* xr = X + (size_t)row * ncols;
    float a0 = 0.f, a1 = 0.f, b0 = 0.f, b1 = 0.f;
    if (c < ncols) {
        float v0 = xr[c], v1 = xr[c + 1];
        a0 = fmaxf(fmaf(v0, s1[c], t1[c]), 0.f);
        a1 = fmaxf(fmaf(v1, s1[c + 1], t1[c + 1]), 0.f);
        b0 = fmaxf(fmaf(v0, s2[c], t2[c]), 0.f);
        b1 = fmaxf(fmaf(v1, s2[c + 1], t2[c + 1]), 0.f);
    }
    size_t o = (size_t)row * ldo + c;
    *(__half2*)(XA + o) = __floats2half2_rn(a0, a1);
    *(__half2*)(XB + o) = __floats2half2_rn(b0, b1);
}

__global__ __launch_bounds__(256) void bn2_kernel(
    const float* __restrict__ X2, const float* __restrict__ kin, const float* __restrict__ ss) {
    int j = blockIdx.x * blockDim.x + threadIdx.x;
    if (j >= D_SEQ_ / 2) return;
    int row = blockIdx.y;
    const float* s1; const float* t1; const float* s2; const float* t2;
    const float* xr; __half* oA; __half* oB; size_t orow;
    if (row < M_) {
        s1 = ss + 4 * EMB2_;  t1 = ss + 5 * EMB2_;
        s2 = ss + 6 * EMB2_;  t2 = ss + 7 * EMB2_;
        xr = X2 + (size_t)row * D_SEQ_;
        oA = g_XA; oB = g_XB; orow = (size_t)row * D_SEQ_;
    } else {
        int rb = row - M_;
        s1 = ss + 4 * EMB2_ + D_SEQ_;  t1 = ss + 5 * EMB2_ + D_SEQ_;
        s2 = ss + 6 * EMB2_ + D_SEQ_;  t2 = ss + 7 * EMB2_ + D_SEQ_;
        xr = kin + (size_t)rb * D_SEQ_;
        oA = g_KA; oB = g_KB; orow = (size_t)rb * D_SEQ_;
    }
    int c = j * 2;
    float v0 = xr[c], v1 = xr[c + 1];
    float a0 = fmaxf(fmaf(v0, s1[c], t1[c]), 0.f);
    float a1 = fmaxf(fmaf(v1, s1[c + 1], t1[c + 1]), 0.f);
    float b0 = fmaxf(fmaf(v0, s2[c], t2[c]), 0.f);
    float b1 = fmaxf(fmaf(v1, s2[c + 1], t2[c + 1]), 0.f);
    *(__half2*)(oA + orow + c) = __floats2half2_rn(a0, a1);
    *(__half2*)(oB + orow + c) = __floats2half2_rn(b0, b1);
}

// ---- fp16 GEMM m16n8k16, 128x128x64, 4 warps of 64x64, 3-stage, 2 CTAs/SM ----
__global__ __launch_bounds__(128, 2) void gemm_f16(
    const __half* __restrict__ A, const __half* __restrict__ Wt,
    const float* __restrict__ bias, float* __restrict__ Cf, __half* __restrict__ Ch,
    int lda, int ldw, int ktiles, int Nout, int Nzero, int ldc,
    const float* __restrict__ Q, int ldq,
    const float* __restrict__ T, int ldt, const int* __restrict__ seq,
    const float* __restrict__ Pg, const float* __restrict__ NF,
    const float* __restrict__ avec) {
    extern __shared__ __half smh[];
    const unsigned sA_u = (unsigned)__cvta_generic_to_shared(smh);
    const unsigned sB_u = sA_u + (unsigned)(GSTAGES * GA_BUF) * 2u;

    const int tid  = threadIdx.x;
    const int bm   = blockIdx.y * GBM;
    const int bn   = blockIdx.x * GBN;
    const int warp = tid >> 5, lane = tid & 31;
    const int wm = (warp & 1) << 6;      // 0,64
    const int wn = (warp >> 1) << 6;     // 0,64
    const int g  = lane >> 2, tg = lane & 3;

    const int t    = lane >> 3;
    const int a_m  = ((t & 1) << 3) + (lane & 7);
    const int a_ko = (t >> 1) << 3;
    const int b_n  = ((t >> 1) << 3) + (lane & 7);
    const int b_ko = (t & 1) << 3;

    float acc[4][8][4];
    #pragma unroll
    for (int mt = 0; mt < 4; ++mt)
        #pragma unroll
        for (int nt = 0; nt < 8; ++nt)
            #pragma unroll
            for (int i = 0; i < 4; ++i) acc[mt][nt][i] = 0.f;

    auto load_stage = [&](int kt, int buf) {
        const int k0 = kt * 64;
        unsigned sab = sA_u + (unsigned)(buf * GA_BUF) * 2u;
        #pragma unroll
        for (int it = 0; it < 8; ++it) {
            int idx = tid + it * 128;
            int row = idx >> 3, seg = idx & 7;
            cp16u(sab + (unsigned)(row * HS + seg * 8) * 2u,
                  A + (size_t)(bm + row) * lda + k0 + seg * 8);
        }
        unsigned sbb = sB_u + (unsigned)(buf * GB_BUF) * 2u;
        #pragma unroll
        for (int it = 0; it < 8; ++it) {
            int idx = tid + it * 128;
            int row = idx >> 3, seg = idx & 7;
            cp16u(sbb + (unsigned)(row * HS + seg * 8) * 2u,
                  Wt + (size_t)(bn + row) * ldw + k0 + seg * 8);
        }
        asm volatile("cp.async.commit_group;\n");
    };

    auto compute = [&](int buf) {
        const unsigned pA = sA_u + (unsigned)(buf * GA_BUF) * 2u;
        const unsigned pB = sB_u + (unsigned)(buf * GB_BUF) * 2u;
        #pragma unroll
        for (int kk = 0; kk < 4; ++kk) {
            unsigned af[4][4], bf[8][2];
            #pragma unroll
            for (int mt = 0; mt < 4; ++mt) {
                unsigned addr = pA + (unsigned)(((wm + (mt << 4) + a_m) * HS
                                                + (kk << 4) + a_ko) << 1);
                ldm4(af[mt][0], af[mt][1], af[mt][2], af[mt][3], addr);
            }
            #pragma unroll
            for (int p = 0; p < 4; ++p) {
                unsigned addr = pB + (unsigned)(((wn + (p << 4) + b_n) * HS
                                                + (kk << 4) + b_ko) << 1);
                ldm4(bf[2*p][0], bf[2*p][1], bf[2*p+1][0], bf[2*p+1][1], addr);
            }
            #pragma unroll
            for (int mt = 0; mt < 4; ++mt)
                #pragma unroll
                for (int nt = 0; nt < 8; ++nt)
                    mma_f16(acc[mt][nt], af[mt], bf[nt]);
        }
    };

    #pragma unroll
    for (int s = 0; s < GSTAGES - 1; ++s) load_stage(s, s);

    for (int kt = 0; kt < ktiles; ++kt) {
        asm volatile("cp.async.wait_group %0;\n" :: "n"(GSTAGES - 2));
        __syncthreads();
        int nxt = kt + GSTAGES - 1;
        if (nxt < ktiles) load_stage(nxt, nxt % GSTAGES);
        else asm volatile("cp.async.commit_group;\n");
        compute(kt % GSTAGES);
    }

    float ca0 = 0.f, ca1 = 0.f;
    if (avec) { ca0 = avec[0]; ca1 = avec[1]; }

    #pragma unroll
    for (int mt = 0; mt < 4; ++mt) {
        int r = bm + wm + (mt << 4);
        int m0 = r + g, m1 = r + g + 8;
        const float* q0 = Q ? Q + (size_t)(m0 / 11) * ldq : nullptr;
        const float* q1 = Q ? Q + (size_t)(m1 / 11) * ldq : nullptr;
        const float* t0 = T ? T + (size_t)seq[m0] * ldt : nullptr;
        const float* t1p = T ? T + (size_t)seq[m1] * ldt : nullptr;
        #pragma unroll
        for (int nt = 0; nt < 8; ++nt) {
            int c = bn + wn + (nt << 3) + (tg << 1);
            #pragma unroll
            for (int half = 0; half < 2; ++half) {
                int cc = c + half;
                if (cc >= Nzero) continue;
                float v0 = 0.f, v1 = 0.f;
                if (cc < Nout) {
                    float bb = bias ? bias[cc] : 0.f;
                    v0 = acc[mt][nt][half]     + bb;
                    v1 = acc[mt][nt][half + 2] + bb;
                    if (q0) { v0 += q0[cc]; v1 += q1[cc]; }
                    if (t0) { v0 += t0[cc]; v1 += t1p[cc]; }
                }
                if (avec) {
                    float p0 = Pg[(size_t)m0 * ldc + cc], n0v = NF[(size_t)m0 * ldc + cc];
                    float p1 = Pg[(size_t)m1 * ldc + cc], n1v = NF[(size_t)m1 * ldc + cc];
                    Cf[(size_t)m0 * ldc + cc] = sigmoidf_(p0) * n0v * ca0 + v0 * ca1;
                    Cf[(size_t)m1 * ldc + cc] = sigmoidf_(p1) * n1v * ca0 + v1 * ca1;
                } else if (Ch) {
                    Ch[(size_t)m0 * ldc + cc] = __float2half(fmaxf(v0, 0.f));
                    Ch[(size_t)m1 * ldc + cc] = __float2half(fmaxf(v1, 0.f));
                } else if (cc < Nout) {
                    Cf[(size_t)m0 * ldc + cc] = v0;
                    Cf[(size_t)m1 * ldc + cc] = v1;
                }
            }
        }
    }
}

__global__ __launch_bounds__(256) void final_kernel(
    const float* __restrict__ G1, const float* __restrict__ G2,
    const float* __restrict__ X2, const float* __restrict__ a2,
    float* __restrict__ out) {
    int b = blockIdx.x;
    float s0 = a2[0], s1 = a2[1];
    for (int i = threadIdx.x; i < D_SEQ_ / 4; i += blockDim.x) {
        float4 acc = make_float4(0.f, 0.f, 0.f, 0.f);
        for (int k = 0; k < K_; ++k) {
            size_t m = (size_t)b * K_ + k;
            float4 f1 = *(const float4*)(G1 + m * D_SEQ_ + i * 4);
            float4 f2 = *(const float4*)(G2 + m * D_SEQ_ + i * 4);
            float4 gn = *(const float4*)(X2 + m * D_SEQ_ + i * 4);
            acc.x += sigmoidf_(f1.x) * gn.x * s0 + f2.x * s1;
            acc.y += sigmoidf_(f1.y) * gn.y * s0 + f2.y * s1;
            acc.z += sigmoidf_(f1.z) * gn.z * s0 + f2.z * s1;
            acc.w += sigmoidf_(f1.w) * gn.w * s0 + f2.w * s1;
        }
        *(float4*)(out + (size_t)b * D_SEQ_ + i * 4) = acc;
    }
}

extern "C" void kernel_launch(void* const* d_in, const int* in_sizes, int n_in,
                              void* d_out, int out_size) {
    const float* kin_in   = (const float*)d_in[0];
    const float* sub      = (const float*)d_in[1];
    const float* n2       = (const float*)d_in[2];
    const float* a        = (const float*)d_in[4];
    const float* a2       = (const float*)d_in[5];
    const float* phos     = (const float*)d_in[6];
    const float* g1_gamma = (const float*)d_in[7];
    const float* g1_beta  = (const float*)d_in[8];
    const float* g1_W     = (const float*)d_in[9];
    const float* g1_b     = (const float*)d_in[10];
    const float* r1_gamma = (const float*)d_in[11];
    const float* r1_beta  = (const float*)d_in[12];
    const float* r1_W1    = (const float*)d_in[13];
    const float* r1_b1    = (const float*)d_in[14];
    const float* r1_W2    = (const float*)d_in[15];
    const float* r1_b2    = (const float*)d_in[16];
    const float* g2_gamma = (const float*)d_in[17];
    const float* g2_beta  = (const float*)d_in[18];
    const float* g2_W     = (const float*)d_in[19];
    const float* g2_b     = (const float*)d_in[20];
    const float* r2_gamma = (const float*)d_in[21];
    const float* r2_beta  = (const float*)d_in[22];
    const float* r2_W1    = (const float*)d_in[23];
    const float* r2_b1    = (const float*)d_in[24];
    const float* r2_W2    = (const float*)d_in[25];
    const float* r2_b2    = (const float*)d_in[26];
    const int*   position = (const int*)d_in[27];
    const int*   raw_seq  = (const int*)d_in[28];

    float* out = (float*)d_out;
    float* graph_feature = out;
    float* node_feature  = out + (size_t)B_ * D_SEQ_;

    float *X, *P1, *P2, *kin, *Qg, *Qr, *Tg, *Tr, *psum, *psq, *psumK, *psqK, *ss;
    int* cnt;
    __half *Y, *XA, *XB, *KA, *KB, *Wt;
    cudaGetSymbolAddress((void**)&X,     g_X);
    cudaGetSymbolAddress((void**)&Y,     g_Y);
    cudaGetSymbolAddress((void**)&XA,    g_XA);
    cudaGetSymbolAddress((void**)&XB,    g_XB);
    cudaGetSymbolAddress((void**)&KA,    g_KA);
    cudaGetSymbolAddress((void**)&KB,    g_KB);
    cudaGetSymbolAddress((void**)&P1,    g_P1);
    cudaGetSymbolAddress((void**)&P2,    g_P2);
    cudaGetSymbolAddress((void**)&Wt,    g_Wt);
    cudaGetSymbolAddress((void**)&kin,   g_kin);
    cudaGetSymbolAddress((void**)&Qg,    g_Qg);
    cudaGetSymbolAddress((void**)&Qr,    g_Qr);
    cudaGetSymbolAddress((void**)&Tg,    g_Tg);
    cudaGetSymbolAddress((void**)&Tr,    g_Tr);
    cudaGetSymbolAddress((void**)&cnt,   g_cnt);
    cudaGetSymbolAddress((void**)&psum,  g_psum);
    cudaGetSymbolAddress((void**)&psq,   g_psq);
    cudaGetSymbolAddress((void**)&psumK, g_psumK);
    cudaGetSymbolAddress((void**)&psqK,  g_psqK);
    cudaGetSymbolAddress((void**)&ss,    g_ss);

    cudaFuncSetAttribute(gemm_f16, cudaFuncAttributeMaxDynamicSharedMemorySize, GSMEM_BYTES);

    float* s_g1 = ss + 0 * EMB2_;  float* t_g1 = ss + 1 * EMB2_;
    float* s_r1 = ss + 2 * EMB2_;  float* t_r1 = ss + 3 * EMB2_;
    float* s_g2 = ss + 4 * EMB2_;  float* t_g2 = ss + 5 * EMB2_;
    float* s_r2 = ss + 6 * EMB2_;  float* t_r2 = ss + 7 * EMB2_;

    __half* Wt_g1  = Wt;
    __half* Wt_r11 = Wt_g1  + (size_t)1280 * KP1;
    __half* Wt_r12 = Wt_r11 + (size_t)1792 * KP1;
    __half* Wt_g2  = Wt_r12 + (size_t)1280 * KP1;
    __half* Wt_r21 = Wt_g2  + (size_t)1280 * KP2;
    __half* Wt_r22 = Wt_r21 + (size_t)NP_R21 * KP2;

    prep_kernel<<<21392 + B_ * (K_ + 1), 256>>>(
        g1_W, r1_W1, r1_W2, g2_W, r2_W1, r2_W2,
        Wt_g1, Wt_r11, Wt_r12, Wt_g2, Wt_r21, Wt_r22,
        kin_in, sub, n2, phos, position, kin, X, node_feature);

    colstats_partial<<<dim3((EMB_ + 255) / 256, NCHUNK_), 256>>>(X, psum, psq, EMB_, M_ / NCHUNK_);
    finalize_stats<<<(EMB_ + 255) / 256, 256>>>(psum, psq, EMB_,
        g1_gamma, g1_beta, r1_gamma, r1_beta, s_g1, t_g1, s_r1, t_r1);
    bn_transform_kernel<<<dim3((KP1 / 2 + 255) / 256, M_), 256>>>(
        X, s_g1, t_g1, s_r1, t_r1, XA, XB, EMB_, KP1, KP1 / 2);

    // stage-1 GEMMs; GEMM3 fuses combine1 -> X2 (ld 1280)
    gemm_f16<<<dim3(10, 88), 128, GSMEM_BYTES>>>(XA, Wt_g1,  g1_b,  P1, nullptr, KP1, KP1, 28, 1280, 1280, 1280, nullptr, 0, nullptr, 0, nullptr, nullptr, nullptr, nullptr);
    gemm_f16<<<dim3(14, 88), 128, GSMEM_BYTES>>>(XB, Wt_r11, r1_b1, nullptr, Y,   KP1, KP1, 28, 1792, 1792, KP1,  nullptr, 0, nullptr, 0, nullptr, nullptr, nullptr, nullptr);
    gemm_f16<<<dim3(10, 88), 128, GSMEM_BYTES>>>(Y,  Wt_r12, r1_b2, X,  nullptr, KP1, KP1, 28, 1280, 1280, 1280, nullptr, 0, nullptr, 0, nullptr, P1, node_feature, a);

    stats2_kernel<<<241, 256>>>(X, kin, raw_seq, psum, psq, psumK, psqK, cnt);
    finalize_stats2<<<(EMB2_ + 255) / 256, 256>>>(psum, psq, psumK, psqK, cnt,
        g2_gamma, g2_beta, r2_gamma, r2_beta, s_g2, t_g2, s_r2, t_r2);

    bn2_kernel<<<dim3(3, M_ + B_), 256>>>(X, kin, ss);
    props_merged<<<(21 * (1280 + EMB2_) + 255) / 256, 256>>>(
        g2_W, r2_W1, s_g2 + 2 * D_SEQ_, t_g2 + 2 * D_SEQ_,
        s_r2 + 2 * D_SEQ_, t_r2 + 2 * D_SEQ_, Tg, Tr);

    // kin GEMMs (Q tables)
    gemm_f16<<<dim3(10, 8), 128, GSMEM_BYTES>>>(KA, Wt_g2  + 1280, nullptr, Qg, nullptr, D_SEQ_, KP2, 20, 1280, 1280, 1280, nullptr, 0, nullptr, 0, nullptr, nullptr, nullptr, nullptr);
    gemm_f16<<<dim3(21, 8), 128, GSMEM_BYTES>>>(KB, Wt_r21 + 1280, nullptr, Qr, nullptr, D_SEQ_, KP2, 20, EMB2_, EMB2_, EMB2_, nullptr, 0, nullptr, 0, nullptr, nullptr, nullptr, nullptr);

    // stage-2 main GEMMs (K=1280) with Q/T epilogue, then r22 (K=2624)
    gemm_f16<<<dim3(10, 88), 128, GSMEM_BYTES>>>(XA, Wt_g2,  g2_b,  P1, nullptr, D_SEQ_, KP2, 20, 1280, 1280, 1280, Qg, 1280, Tg, 1280, raw_seq, nullptr, nullptr, nullptr);
    gemm_f16<<<dim3(21, 88), 128, GSMEM_BYTES>>>(XB, Wt_r21, r2_b1, nullptr, Y,   D_SEQ_, KP2, 20, EMB2_, KP2, KP2,  Qr, EMB2_, Tr, EMB2_, raw_seq, nullptr, nullptr, nullptr);
    gemm_f16<<<dim3(10, 88), 128, GSMEM_BYTES>>>(Y,  Wt_r22, r2_b2, P2, nullptr, KP2, KP2, 41, 1280, 1280, 1280, nullptr, 0, nullptr, 0, nullptr, nullptr, nullptr, nullptr);

    final_kernel<<<B_, 256>>>(P1, P2, X, a2, graph_feature);
}

// round 13
// speedup vs baseline: 1.1127x; 1.1127x over previous
#include <cuda_runtime.h>
#include <cuda_fp16.h>
#include <cstdint>

#define B_      1024
#define K_      11
#define L_KIN_  128
#define L_SUB_  64
#define L_STR_  128
#define D_SEQ_  1280
#define D_STR_  512
#define EMB_    1792
#define EMB2_   2564
#define M_      (B_ * K_)
#define NCHUNK_ 44
#define KP1     1792
#define KP2     2624
#define NP_R21  2816
#define NB_BUILD (B_ * (K_ + 1))   // 12288

#define GBM 128
#define GBN 128
#define GSTAGES 3
#define HS 72
#define GA_BUF (GBM * HS)
#define GB_BUF (GBN * HS)
#define GSMEM_BYTES (GSTAGES * (GA_BUF + GB_BUF) * 2)   // 110592

__device__ float  g_X [(size_t)M_ * EMB_];
__device__ __half g_Y [(size_t)M_ * KP2];
__device__ __half g_XA[(size_t)M_ * KP1];
__device__ __half g_XB[(size_t)M_ * KP1];
__device__ __half g_KA[(size_t)B_ * D_SEQ_];
__device__ __half g_KB[(size_t)B_ * D_SEQ_];
__device__ float  g_P1[(size_t)M_ * D_SEQ_];
__device__ float  g_P2[(size_t)M_ * D_SEQ_];
__device__ __half g_Wt[21905408];
__device__ float  g_kin[(size_t)B_ * D_SEQ_];
__device__ float  g_Qg[(size_t)B_ * D_SEQ_];
__device__ float  g_Qr[(size_t)B_ * EMB2_];
__device__ float  g_Tg[21 * D_SEQ_];
__device__ float  g_Tr[21 * EMB2_];
__device__ int    g_cnt[21];
__device__ float  g_psum [NCHUNK_ * EMB_];
__device__ float  g_psq  [NCHUNK_ * EMB_];
__device__ float  g_psumK[4 * D_SEQ_];
__device__ float  g_psqK [4 * D_SEQ_];
__device__ float  g_ss  [8 * EMB2_];

__constant__ float c_props[21 * 4] = {
    0,0,0,0,  1,0,0,0,  0,0,0,0,  0,0,0,0,  1,0,0,0,  0,0,0,0,  0,0,0,0,
    1,0,0,0,  1,0,0,0,  0,0,0,0,  0,0,1,0,  0,0,0,0,  0,0,0,1,  0,0,1,0,
    1,0,0,0,  0,0,0,1,  0,1,0,0,  0,0,0,1,  0,1,0,0,  0,1,0,0,  0,0,0,0
};

__device__ __forceinline__ float sigmoidf_(float x) { return 1.f / (1.f + expf(-x)); }

__device__ __forceinline__ void mma_f16(float* d, const unsigned* a, const unsigned* b) {
    asm volatile(
        "mma.sync.aligned.m16n8k16.row.col.f32.f16.f16.f32 "
        "{%0,%1,%2,%3}, {%4,%5,%6,%7}, {%8,%9}, {%0,%1,%2,%3};\n"
        : "+f"(d[0]), "+f"(d[1]), "+f"(d[2]), "+f"(d[3])
        : "r"(a[0]), "r"(a[1]), "r"(a[2]), "r"(a[3]), "r"(b[0]), "r"(b[1]));
}
__device__ __forceinline__ void cp16u(unsigned dst, const void* src) {
    asm volatile("cp.async.cg.shared.global [%0], [%1], 16;\n" :: "r"(dst), "l"(src));
}
__device__ __forceinline__ void ldm4(unsigned& r0, unsigned& r1, unsigned& r2, unsigned& r3,
                                     unsigned addr) {
    asm volatile("ldmatrix.sync.aligned.m8n8.x4.shared.b16 {%0,%1,%2,%3}, [%4];"
                 : "=r"(r0), "=r"(r1), "=r"(r2), "=r"(r3) : "r"(addr));
}

// ---- prep: heavy build/kin blocks FIRST (0..12287), weight transpose after ----
__global__ __launch_bounds__(256) void prep_kernel(
    const float* __restrict__ W0, const float* __restrict__ W1, const float* __restrict__ W2,
    const float* __restrict__ W3, const float* __restrict__ W4, const float* __restrict__ W5,
    __half* __restrict__ D0, __half* __restrict__ D1, __half* __restrict__ D2,
    __half* __restrict__ D3, __half* __restrict__ D4, __half* __restrict__ D5,
    const float* __restrict__ kin_in, const float* __restrict__ sub,
    const float* __restrict__ n2, const float* __restrict__ phos,
    const int* __restrict__ position,
    float* __restrict__ kin_out, float* __restrict__ X, float* __restrict__ node_feature) {
    __shared__ float t[32][33];
    int bx = blockIdx.x;
    if (bx < NB_BUILD) {
        int b = bx / (K_ + 1), k = bx % (K_ + 1);
        if (k == K_) {   // kin mean (dominant DRAM traffic; runs in the first waves)
            const float* base = kin_in + ((size_t)b * L_KIN_ + 1) * D_SEQ_;
            for (int i = threadIdx.x; i < D_SEQ_ / 4; i += blockDim.x) {
                float4 acc = make_float4(0.f, 0.f, 0.f, 0.f);
                #pragma unroll 8
                for (int r = 0; r < L_KIN_ - 1; ++r) {
                    float4 v = *(const float4*)(base + (size_t)r * D_SEQ_ + i * 4);
                    acc.x += v.x; acc.y += v.y; acc.z += v.z; acc.w += v.w;
                }
                const float inv = 1.f / 127.f;
                *(float4*)(kin_out + (size_t)b * D_SEQ_ + i * 4) =
                    make_float4(acc.x * inv, acc.y * inv, acc.z * inv, acc.w * inv);
            }
            return;
        }
        size_t m = (size_t)b * K_ + k;
        const float* src1 = sub + ((size_t)b * L_SUB_ + 1 + k) * D_SEQ_;
        float* dst = X + m * EMB_;
        float* nf  = node_feature + m * D_SEQ_;
        bool mid = (k == K_ / 2);
        for (int i = threadIdx.x; i < D_SEQ_ / 4; i += blockDim.x) {
            float4 v = *(const float4*)(src1 + i * 4);
            *(float4*)(nf + i * 4) = v;
            if (mid) {
                float4 p = *(const float4*)(phos + i * 4);
                v.x += p.x; v.y += p.y; v.z += p.z; v.w += p.w;
            }
            *(float4*)(dst + i * 4) = v;
        }
        int row = position[b] + k - K_ / 2;
        bool ok = (row >= 0 && row < L_STR_);
        const float* src2 = n2 + ((size_t)b * L_STR_ + (ok ? row : 0)) * D_STR_;
        for (int i = threadIdx.x; i < D_STR_ / 4; i += blockDim.x) {
            float4 v = make_float4(0.f, 0.f, 0.f, 0.f);
            if (ok) v = *(const float4*)(src2 + i * 4);
            if (mid) {
                float4 p = *(const float4*)(phos + D_SEQ_ + i * 4);
                v.x += p.x; v.y += p.y; v.z += p.z; v.w += p.w;
            }
            *(float4*)(dst + D_SEQ_ + i * 4) = v;
        }
        return;
    }
    bx -= NB_BUILD;
    const float* W; __half* D; int K, N, KP, kb, blk;
    if      (bx < 2240)  { W=W0; D=D0; K=EMB_;  N=1280;  KP=KP1; kb=56; blk=bx; }
    else if (bx < 5376)  { W=W1; D=D1; K=EMB_;  N=1792;  KP=KP1; kb=56; blk=bx-2240; }
    else if (bx < 7616)  { W=W2; D=D2; K=EMB_;  N=1280;  KP=KP1; kb=56; blk=bx-5376; }
    else if (bx < 10896) { W=W3; D=D3; K=EMB2_; N=1280;  KP=KP2; kb=82; blk=bx-7616; }
    else if (bx < 18112) { W=W4; D=D4; K=EMB2_; N=EMB2_; KP=KP2; kb=82; blk=bx-10896; }
    else                 { W=W5; D=D5; K=EMB2_; N=1280;  KP=KP2; kb=82; blk=bx-18112; }
    int k0 = (blk % kb) * 32, n0 = (blk / kb) * 32;
    int tx = threadIdx.x & 31, ty = threadIdx.x >> 5;
    #pragma unroll
    for (int j = 0; j < 4; ++j) {
        int k = k0 + ty + j * 8, n = n0 + tx;
        t[ty + j * 8][tx] = (k < K && n < N) ? W[(size_t)k * N + n] : 0.f;
    }
    __syncthreads();
    #pragma unroll
    for (int j = 0; j < 4; ++j) {
        int n = n0 + ty + j * 8, k = k0 + tx;
        D[(size_t)n * KP + k] = __float2half(t[tx][ty + j * 8]);
    }
}

__global__ __launch_bounds__(256) void colstats_partial(
    const float* __restrict__ X, float* __restrict__ psum, float* __restrict__ psq,
    int ncols, int rows_per_chunk) {
    int col = blockIdx.x * blockDim.x + threadIdx.x;
    if (col >= ncols) return;
    int r0 = blockIdx.y * rows_per_chunk;
    float s = 0.f, q = 0.f;
    const float* p = X + (size_t)r0 * ncols + col;
    #pragma unroll 8
    for (int r = 0; r < rows_per_chunk; ++r, p += ncols) {
        float v = *p;
        s += v; q += v * v;
    }
    psum[blockIdx.y * ncols + col] = s;
    psq [blockIdx.y * ncols + col] = q;
}

__global__ __launch_bounds__(256) void finalize_stats(
    const float* __restrict__ psum, const float* __restrict__ psq, int ncols,
    const float* __restrict__ gA, const float* __restrict__ bA,
    const float* __restrict__ gB, const float* __restrict__ bB,
    float* __restrict__ sA, float* __restrict__ tA,
    float* __restrict__ sB, float* __restrict__ tB) {
    int col = blockIdx.x * blockDim.x + threadIdx.x;
    if (col >= ncols) return;
    float s = 0.f, q = 0.f;
    for (int c = 0; c < NCHUNK_; ++c) {
        s += psum[c * ncols + col];
        q += psq [c * ncols + col];
    }
    const float inv_n = 1.f / (float)M_;
    float mean = s * inv_n;
    float var  = q * inv_n - mean * mean;
    float inv  = rsqrtf(var + 1e-5f);
    float sa = gA[col] * inv; sA[col] = sa; tA[col] = bA[col] - mean * sa;
    float sb = gB[col] * inv; sB[col] = sb; tB[col] = bB[col] - mean * sb;
}

// ---- merged stage-2 stats: X2 chunks (0..219), kin chunks (220..239), hist (240) ----
__global__ __launch_bounds__(256) void stats2_kernel(
    const float* __restrict__ X2, const float* __restrict__ kin, const int* __restrict__ seq,
    float* __restrict__ psum, float* __restrict__ psq,
    float* __restrict__ psumK, float* __restrict__ psqK, int* __restrict__ cnt) {
    int bx = blockIdx.x;
    if (bx < 220) {
        int col = (bx % 5) * 256 + threadIdx.x;
        int chunk = bx / 5;
        float s = 0.f, q = 0.f;
        const float* p = X2 + (size_t)chunk * 256 * D_SEQ_ + col;
        #pragma unroll 8
        for (int r = 0; r < 256; ++r, p += D_SEQ_) { float v = *p; s += v; q += v * v; }
        psum[chunk * D_SEQ_ + col] = s;
        psq [chunk * D_SEQ_ + col] = q;
    } else if (bx < 240) {
        int b2 = bx - 220;
        int col = (b2 % 5) * 256 + threadIdx.x;
        int chunk = b2 / 5;
        float s = 0.f, q = 0.f;
        const float* p = kin + (size_t)chunk * 256 * D_SEQ_ + col;
        #pragma unroll 8
        for (int r = 0; r < 256; ++r, p += D_SEQ_) { float v = *p; s += v; q += v * v; }
        psumK[chunk * D_SEQ_ + col] = s;
        psqK [chunk * D_SEQ_ + col] = q;
    } else {
        __shared__ int h[21];
        if (threadIdx.x < 21) h[threadIdx.x] = 0;
        __syncthreads();
        for (int i = threadIdx.x; i < M_; i += blockDim.x) atomicAdd(&h[seq[i]], 1);
        __syncthreads();
        if (threadIdx.x < 21) cnt[threadIdx.x] = h[threadIdx.x];
    }
}

__global__ __launch_bounds__(256) void finalize_stats2(
    const float* __restrict__ psum, const float* __restrict__ psq,
    const float* __restrict__ psumK, const float* __restrict__ psqK,
    const int* __restrict__ cnt,
    const float* __restrict__ gA, const float* __restrict__ bA,
    const float* __restrict__ gB, const float* __restrict__ bB,
    float* __restrict__ sA, float* __restrict__ tA,
    float* __restrict__ sB, float* __restrict__ tB) {
    int col = blockIdx.x * blockDim.x + threadIdx.x;
    if (col >= EMB2_) return;
    float mean, var;
    if (col < D_SEQ_) {
        float s = 0.f, q = 0.f;
        for (int c = 0; c < NCHUNK_; ++c) { s += psum[c * D_SEQ_ + col]; q += psq[c * D_SEQ_ + col]; }
        mean = s / (float)M_; var = q / (float)M_ - mean * mean;
    } else if (col < 2 * D_SEQ_) {
        int j = col - D_SEQ_;
        float s = 0.f, q = 0.f;
        for (int c = 0; c < 4; ++c) { s += psumK[c * D_SEQ_ + j]; q += psqK[c * D_SEQ_ + j]; }
        mean = s / (float)B_; var = q / (float)B_ - mean * mean;
    } else {
        int j = col - 2 * D_SEQ_;
        float s = 0.f;
        for (int sd = 0; sd < 21; ++sd) s += (float)cnt[sd] * c_props[sd * 4 + j];
        mean = s / (float)M_; var = mean - mean * mean;
    }
    float inv = rsqrtf(var + 1e-5f);
    float sa = gA[col] * inv; sA[col] = sa; tA[col] = bA[col] - mean * sa;
    float sb = gB[col] * inv; sB[col] = sb; tB[col] = bB[col] - mean * sb;
}

__global__ __launch_bounds__(256) void props_merged(
    const float* __restrict__ Wg, const float* __restrict__ Wr,
    const float* __restrict__ sg, const float* __restrict__ tg,
    const float* __restrict__ sr, const float* __restrict__ tr,
    float* __restrict__ Tg, float* __restrict__ Tr) {
    int idx = blockIdx.x * blockDim.x + threadIdx.x;
    const float* W; const float* s; const float* t; float* T; int N; int i;
    if (idx < 21 * 1280) { W = Wg; s = sg; t = tg; T = Tg; N = 1280; i = idx; }
    else {
        i = idx - 21 * 1280;
        if (i >= 21 * EMB2_) return;
        W = Wr; s = sr; t = tr; T = Tr; N = EMB2_;
    }
    int sid = i / N, n = i % N;
    float acc = 0.f;
    #pragma unroll
    for (int j = 0; j < 4; ++j) {
        float pv = fmaxf(fmaf(c_props[sid * 4 + j], s[j], t[j]), 0.f);
        acc += pv * W[(size_t)(2 * D_SEQ_ + j) * N + n];
    }
    T[i] = acc;
}

__global__ __launch_bounds__(256) void bn_transform_kernel(
    const float* __restrict__ X,
    const float* __restrict__ s1, const float* __restrict__ t1,
    const float* __restrict__ s2, const float* __restrict__ t2,
    __half* __restrict__ XA, __half* __restrict__ XB, int ncols, int ldo, int nj) {
    int j = blockIdx.x * blockDim.x + threadIdx.x;
    if (j >= nj) return;
    int row = blockIdx.y;
    int c = j * 2;
    const float* xr = X + (size_t)row * ncols;
    float a0 = 0.f, a1 = 0.f, b0 = 0.f, b1 = 0.f;
    if (c < ncols) {
        float v0 = xr[c], v1 = xr[c + 1];
        a0 = fmaxf(fmaf(v0, s1[c], t1[c]), 0.f);
        a1 = fmaxf(fmaf(v1, s1[c + 1], t1[c + 1]), 0.f);
        b0 = fmaxf(fmaf(v0, s2[c], t2[c]), 0.f);
        b1 = fmaxf(fmaf(v1, s2[c + 1], t2[c + 1]), 0.f);
    }
    size_t o = (size_t)row * ldo + c;
    *(__half2*)(XA + o) = __floats2half2_rn(a0, a1);
    *(__half2*)(XB + o) = __floats2half2_rn(b0, b1);
}

__global__ __launch_bounds__(256) void bn2_kernel(
    const float* __restrict__ X2, const float* __restrict__ kin, const float* __restrict__ ss) {
    int j = blockIdx.x * blockDim.x + threadIdx.x;
    if (j >= D_SEQ_ / 2) return;
    int row = blockIdx.y;
    const float* s1; const float* t1; const float* s2; const float* t2;
    const float* xr; __half* oA; __half* oB; size_t orow;
    if (row < M_) {
        s1 = ss + 4 * EMB2_;  t1 = ss + 5 * EMB2_;
        s2 = ss + 6 * EMB2_;  t2 = ss + 7 * EMB2_;
        xr = X2 + (size_t)row * D_SEQ_;
        oA = g_XA; oB = g_XB; orow = (size_t)row * D_SEQ_;
    } else {
        int rb = row - M_;
        s1 = ss + 4 * EMB2_ + D_SEQ_;  t1 = ss + 5 * EMB2_ + D_SEQ_;
        s2 = ss + 6 * EMB2_ + D_SEQ_;  t2 = ss + 7 * EMB2_ + D_SEQ_;
        xr = kin + (size_t)rb * D_SEQ_;
        oA = g_KA; oB = g_KB; orow = (size_t)rb * D_SEQ_;
    }
    int c = j * 2;
    float v0 = xr[c], v1 = xr[c + 1];
    float a0 = fmaxf(fmaf(v0, s1[c], t1[c]), 0.f);
    float a1 = fmaxf(fmaf(v1, s1[c + 1], t1[c + 1]), 0.f);
    float b0 = fmaxf(fmaf(v0, s2[c], t2[c]), 0.f);
    float b1 = fmaxf(fmaf(v1, s2[c + 1], t2[c + 1]), 0.f);
    *(__half2*)(oA + orow + c) = __floats2half2_rn(a0, a1);
    *(__half2*)(oB + orow + c) = __floats2half2_rn(b0, b1);
}

// ---- fp16 GEMM m16n8k16, 128x128x64, 8 warps of 64x32, 3-stage, 2 CTAs/SM (R10 config) ----
__global__ __launch_bounds__(256, 2) void gemm_f16(
    const __half* __restrict__ A, const __half* __restrict__ Wt,
    const float* __restrict__ bias, float* __restrict__ Cf, __half* __restrict__ Ch,
    int lda, int ldw, int ktiles, int Nout, int Nzero, int ldc,
    const float* __restrict__ Q, int ldq,
    const float* __restrict__ T, int ldt, const int* __restrict__ seq,
    const float* __restrict__ Pg, const float* __restrict__ NF,
    const float* __restrict__ avec) {
    extern __shared__ __half smh[];
    const unsigned sA_u = (unsigned)__cvta_generic_to_shared(smh);
    const unsigned sB_u = sA_u + (unsigned)(GSTAGES * GA_BUF) * 2u;

    const int tid  = threadIdx.x;
    const int bm   = blockIdx.y * GBM;
    const int bn   = blockIdx.x * GBN;
    const int warp = tid >> 5, lane = tid & 31;
    const int wm = (warp & 1) << 6;
    const int wn = (warp >> 1) << 5;
    const int g  = lane >> 2, tg = lane & 3;

    const int t    = lane >> 3;
    const int a_m  = ((t & 1) << 3) + (lane & 7);
    const int a_ko = (t >> 1) << 3;
    const int b_n  = ((t >> 1) << 3) + (lane & 7);
    const int b_ko = (t & 1) << 3;

    float acc[4][4][4];
    #pragma unroll
    for (int mt = 0; mt < 4; ++mt)
        #pragma unroll
        for (int nt = 0; nt < 4; ++nt)
            #pragma unroll
            for (int i = 0; i < 4; ++i) acc[mt][nt][i] = 0.f;

    auto load_stage = [&](int kt, int buf) {
        const int k0 = kt * 64;
        unsigned sab = sA_u + (unsigned)(buf * GA_BUF) * 2u;
        #pragma unroll
        for (int it = 0; it < 4; ++it) {
            int idx = tid + it * 256;
            int row = idx >> 3, seg = idx & 7;
            cp16u(sab + (unsigned)(row * HS + seg * 8) * 2u,
                  A + (size_t)(bm + row) * lda + k0 + seg * 8);
        }
        unsigned sbb = sB_u + (unsigned)(buf * GB_BUF) * 2u;
        #pragma unroll
        for (int it = 0; it < 4; ++it) {
            int idx = tid + it * 256;
            int row = idx >> 3, seg = idx & 7;
            cp16u(sbb + (unsigned)(row * HS + seg * 8) * 2u,
                  Wt + (size_t)(bn + row) * ldw + k0 + seg * 8);
        }
        asm volatile("cp.async.commit_group;\n");
    };

    auto compute = [&](int buf) {
        const unsigned pA = sA_u + (unsigned)(buf * GA_BUF) * 2u;
        const unsigned pB = sB_u + (unsigned)(buf * GB_BUF) * 2u;
        #pragma unroll
        for (int kk = 0; kk < 4; ++kk) {
            unsigned af[4][4], bf[4][2];
            #pragma unroll
            for (int mt = 0; mt < 4; ++mt) {
                unsigned addr = pA + (unsigned)(((wm + (mt << 4) + a_m) * HS
                                                + (kk << 4) + a_ko) << 1);
                ldm4(af[mt][0], af[mt][1], af[mt][2], af[mt][3], addr);
            }
            #pragma unroll
            for (int p = 0; p < 2; ++p) {
                unsigned addr = pB + (unsigned)(((wn + (p << 4) + b_n) * HS
                                                + (kk << 4) + b_ko) << 1);
                ldm4(bf[2*p][0], bf[2*p][1], bf[2*p+1][0], bf[2*p+1][1], addr);
            }
            #pragma unroll
            for (int mt = 0; mt < 4; ++mt)
                #pragma unroll
                for (int nt = 0; nt < 4; ++nt)
                    mma_f16(acc[mt][nt], af[mt], bf[nt]);
        }
    };

    #pragma unroll
    for (int s = 0; s < GSTAGES - 1; ++s) load_stage(s, s);

    for (int kt = 0; kt < ktiles; ++kt) {
        asm volatile("cp.async.wait_group %0;\n" :: "n"(GSTAGES - 2));
        __syncthreads();
        int nxt = kt + GSTAGES - 1;
        if (nxt < ktiles) load_stage(nxt, nxt % GSTAGES);
        else asm volatile("cp.async.commit_group;\n");
        compute(kt % GSTAGES);
    }

    float ca0 = 0.f, ca1 = 0.f;
    if (avec) { ca0 = avec[0]; ca1 = avec[1]; }

    #pragma unroll
    for (int mt = 0; mt < 4; ++mt) {
        int r = bm + wm + (mt << 4);
        int m0 = r + g, m1 = r + g + 8;
        const float* q0 = Q ? Q + (size_t)(m0 / 11) * ldq : nullptr;
        const float* q1 = Q ? Q + (size_t)(m1 / 11) * ldq : nullptr;
        const float* t0 = T ? T + (size_t)seq[m0] * ldt : nullptr;
        const float* t1p = T ? T + (size_t)seq[m1] * ldt : nullptr;
        #pragma unroll
        for (int nt = 0; nt < 4; ++nt) {
            int c = bn + wn + (nt << 3) + (tg << 1);
            #pragma unroll
            for (int half = 0; half < 2; ++half) {
                int cc = c + half;
                if (cc >= Nzero) continue;
                float v0 = 0.f, v1 = 0.f;
                if (cc < Nout) {
                    float bb = bias ? bias[cc] : 0.f;
                    v0 = acc[mt][nt][half]     + bb;
                    v1 = acc[mt][nt][half + 2] + bb;
                    if (q0) { v0 += q0[cc]; v1 += q1[cc]; }
                    if (t0) { v0 += t0[cc]; v1 += t1p[cc]; }
                }
                if (avec) {
                    float p0 = Pg[(size_t)m0 * ldc + cc], n0v = NF[(size_t)m0 * ldc + cc];
                    float p1 = Pg[(size_t)m1 * ldc + cc], n1v = NF[(size_t)m1 * ldc + cc];
                    Cf[(size_t)m0 * ldc + cc] = sigmoidf_(p0) * n0v * ca0 + v0 * ca1;
                    Cf[(size_t)m1 * ldc + cc] = sigmoidf_(p1) * n1v * ca0 + v1 * ca1;
                } else if (Ch) {
                    Ch[(size_t)m0 * ldc + cc] = __float2half(fmaxf(v0, 0.f));
                    Ch[(size_t)m1 * ldc + cc] = __float2half(fmaxf(v1, 0.f));
                } else if (cc < Nout) {
                    Cf[(size_t)m0 * ldc + cc] = v0;
                    Cf[(size_t)m1 * ldc + cc] = v1;
                }
            }
        }
    }
}

__global__ __launch_bounds__(256) void final_kernel(
    const float* __restrict__ G1, const float* __restrict__ G2,
    const float* __restrict__ X2, const float* __restrict__ a2,
    float* __restrict__ out) {
    int b = blockIdx.x;
    float s0 = a2[0], s1 = a2[1];
    for (int i = threadIdx.x; i < D_SEQ_ / 4; i += blockDim.x) {
        float4 acc = make_float4(0.f, 0.f, 0.f, 0.f);
        for (int k = 0; k < K_; ++k) {
            size_t m = (size_t)b * K_ + k;
            float4 f1 = *(const float4*)(G1 + m * D_SEQ_ + i * 4);
            float4 f2 = *(const float4*)(G2 + m * D_SEQ_ + i * 4);
            float4 gn = *(const float4*)(X2 + m * D_SEQ_ + i * 4);
            acc.x += sigmoidf_(f1.x) * gn.x * s0 + f2.x * s1;
            acc.y += sigmoidf_(f1.y) * gn.y * s0 + f2.y * s1;
            acc.z += sigmoidf_(f1.z) * gn.z * s0 + f2.z * s1;
            acc.w += sigmoidf_(f1.w) * gn.w * s0 + f2.w * s1;
        }
        *(float4*)(out + (size_t)b * D_SEQ_ + i * 4) = acc;
    }
}

extern "C" void kernel_launch(void* const* d_in, const int* in_sizes, int n_in,
                              void* d_out, int out_size) {
    const float* kin_in   = (const float*)d_in[0];
    const float* sub      = (const float*)d_in[1];
    const float* n2       = (const float*)d_in[2];
    const float* a        = (const float*)d_in[4];
    const float* a2       = (const float*)d_in[5];
    const float* phos     = (const float*)d_in[6];
    const float* g1_gamma = (const float*)d_in[7];
    const float* g1_beta  = (const float*)d_in[8];
    const float* g1_W     = (const float*)d_in[9];
    const float* g1_b     = (const float*)d_in[10];
    const float* r1_gamma = (const float*)d_in[11];
    const float* r1_beta  = (const float*)d_in[12];
    const float* r1_W1    = (const float*)d_in[13];
    const float* r1_b1    = (const float*)d_in[14];
    const float* r1_W2    = (const float*)d_in[15];
    const float* r1_b2    = (const float*)d_in[16];
    const float* g2_gamma = (const float*)d_in[17];
    const float* g2_beta  = (const float*)d_in[18];
    const float* g2_W     = (const float*)d_in[19];
    const float* g2_b     = (const float*)d_in[20];
    const float* r2_gamma = (const float*)d_in[21];
    const float* r2_beta  = (const float*)d_in[22];
    const float* r2_W1    = (const float*)d_in[23];
    const float* r2_b1    = (const float*)d_in[24];
    const float* r2_W2    = (const float*)d_in[25];
    const float* r2_b2    = (const float*)d_in[26];
    const int*   position = (const int*)d_in[27];
    const int*   raw_seq  = (const int*)d_in[28];

    float* out = (float*)d_out;
    float* graph_feature = out;
    float* node_feature  = out + (size_t)B_ * D_SEQ_;

    float *X, *P1, *P2, *kin, *Qg, *Qr, *Tg, *Tr, *psum, *psq, *psumK, *psqK, *ss;
    int* cnt;
    __half *Y, *XA, *XB, *KA, *KB, *Wt;
    cudaGetSymbolAddress((void**)&X,     g_X);
    cudaGetSymbolAddress((void**)&Y,     g_Y);
    cudaGetSymbolAddress((void**)&XA,    g_XA);
    cudaGetSymbolAddress((void**)&XB,    g_XB);
    cudaGetSymbolAddress((void**)&KA,    g_KA);
    cudaGetSymbolAddress((void**)&KB,    g_KB);
    cudaGetSymbolAddress((void**)&P1,    g_P1);
    cudaGetSymbolAddress((void**)&P2,    g_P2);
    cudaGetSymbolAddress((void**)&Wt,    g_Wt);
    cudaGetSymbolAddress((void**)&kin,   g_kin);
    cudaGetSymbolAddress((void**)&Qg,    g_Qg);
    cudaGetSymbolAddress((void**)&Qr,    g_Qr);
    cudaGetSymbolAddress((void**)&Tg,    g_Tg);
    cudaGetSymbolAddress((void**)&Tr,    g_Tr);
    cudaGetSymbolAddress((void**)&cnt,   g_cnt);
    cudaGetSymbolAddress((void**)&psum,  g_psum);
    cudaGetSymbolAddress((void**)&psq,   g_psq);
    cudaGetSymbolAddress((void**)&psumK, g_psumK);
    cudaGetSymbolAddress((void**)&psqK,  g_psqK);
    cudaGetSymbolAddress((void**)&ss,    g_ss);

    cudaFuncSetAttribute(gemm_f16, cudaFuncAttributeMaxDynamicSharedMemorySize, GSMEM_BYTES);

    float* s_g1 = ss + 0 * EMB2_;  float* t_g1 = ss + 1 * EMB2_;
    float* s_r1 = ss + 2 * EMB2_;  float* t_r1 = ss + 3 * EMB2_;
    float* s_g2 = ss + 4 * EMB2_;  float* t_g2 = ss + 5 * EMB2_;
    float* s_r2 = ss + 6 * EMB2_;  float* t_r2 = ss + 7 * EMB2_;

    __half* Wt_g1  = Wt;
    __half* Wt_r11 = Wt_g1  + (size_t)1280 * KP1;
    __half* Wt_r12 = Wt_r11 + (size_t)1792 * KP1;
    __half* Wt_g2  = Wt_r12 + (size_t)1280 * KP1;
    __half* Wt_r21 = Wt_g2  + (size_t)1280 * KP2;
    __half* Wt_r22 = Wt_r21 + (size_t)NP_R21 * KP2;

    prep_kernel<<<NB_BUILD + 21392, 256>>>(
        g1_W, r1_W1, r1_W2, g2_W, r2_W1, r2_W2,
        Wt_g1, Wt_r11, Wt_r12, Wt_g2, Wt_r21, Wt_r22,
        kin_in, sub, n2, phos, position, kin, X, node_feature);

    colstats_partial<<<dim3((EMB_ + 255) / 256, NCHUNK_), 256>>>(X, psum, psq, EMB_, M_ / NCHUNK_);
    finalize_stats<<<(EMB_ + 255) / 256, 256>>>(psum, psq, EMB_,
        g1_gamma, g1_beta, r1_gamma, r1_beta, s_g1, t_g1, s_r1, t_r1);
    bn_transform_kernel<<<dim3((KP1 / 2 + 255) / 256, M_), 256>>>(
        X, s_g1, t_g1, s_r1, t_r1, XA, XB, EMB_, KP1, KP1 / 2);

    // stage-1 GEMMs; GEMM3 fuses combine1 -> X2 (ld 1280)
    gemm_f16<<<dim3(10, 88), 256, GSMEM_BYTES>>>(XA, Wt_g1,  g1_b,  P1, nullptr, KP1, KP1, 28, 1280, 1280, 1280, nullptr, 0, nullptr, 0, nullptr, nullptr, nullptr, nullptr);
    gemm_f16<<<dim3(14, 88), 256, GSMEM_BYTES>>>(XB, Wt_r11, r1_b1, nullptr, Y,   KP1, KP1, 28, 1792, 1792, KP1,  nullptr, 0, nullptr, 0, nullptr, nullptr, nullptr, nullptr);
    gemm_f16<<<dim3(10, 88), 256, GSMEM_BYTES>>>(Y,  Wt_r12, r1_b2, X,  nullptr, KP1, KP1, 28, 1280, 1280, 1280, nullptr, 0, nullptr, 0, nullptr, P1, node_feature, a);

    stats2_kernel<<<241, 256>>>(X, kin, raw_seq, psum, psq, psumK, psqK, cnt);
    finalize_stats2<<<(EMB2_ + 255) / 256, 256>>>(psum, psq, psumK, psqK, cnt,
        g2_gamma, g2_beta, r2_gamma, r2_beta, s_g2, t_g2, s_r2, t_r2);

    bn2_kernel<<<dim3(3, M_ + B_), 256>>>(X, kin, ss);
    props_merged<<<(21 * (1280 + EMB2_) + 255) / 256, 256>>>(
        g2_W, r2_W1, s_g2 + 2 * D_SEQ_, t_g2 + 2 * D_SEQ_,
        s_r2 + 2 * D_SEQ_, t_r2 + 2 * D_SEQ_, Tg, Tr);

    // kin GEMMs (Q tables)
    gemm_f16<<<dim3(10, 8), 256, GSMEM_BYTES>>>(KA, Wt_g2  + 1280, nullptr, Qg, nullptr, D_SEQ_, KP2, 20, 1280, 1280, 1280, nullptr, 0, nullptr, 0, nullptr, nullptr, nullptr, nullptr);
    gemm_f16<<<dim3(21, 8), 256, GSMEM_BYTES>>>(KB, Wt_r21 + 1280, nullptr, Qr, nullptr, D_SEQ_, KP2, 20, EMB2_, EMB2_, EMB2_, nullptr, 0, nullptr, 0, nullptr, nullptr, nullptr, nullptr);

    // stage-2 main GEMMs (K=1280) with Q/T epilogue, then r22 (K=2624)
    gemm_f16<<<dim3(10, 88), 256, GSMEM_BYTES>>>(XA, Wt_g2,  g2_b,  P1, nullptr, D_SEQ_, KP2, 20, 1280, 1280, 1280, Qg, 1280, Tg, 1280, raw_seq, nullptr, nullptr, nullptr);
    gemm_f16<<<dim3(21, 88), 256, GSMEM_BYTES>>>(XB, Wt_r21, r2_b1, nullptr, Y,   D_SEQ_, KP2, 20, EMB2_, KP2, KP2,  Qr, EMB2_, Tr, EMB2_, raw_seq, nullptr, nullptr, nullptr);
    gemm_f16<<<dim3(10, 88), 256, GSMEM_BYTES>>>(Y,  Wt_r22, r2_b2, P2, nullptr, KP2, KP2, 41, 1280, 1280, 1280, nullptr, 0, nullptr, 0, nullptr, nullptr, nullptr, nullptr);

    final_kernel<<<B_, 256>>>(P1, P2, X, a2, graph_feature);
}

// round 14
// speedup vs baseline: 1.1605x; 1.0430x over previous
#include <cuda_runtime.h>
#include <cuda_fp16.h>
#include <cstdint>

#define B_      1024
#define K_      11
#define L_KIN_  128
#define L_SUB_  64
#define L_STR_  128
#define D_SEQ_  1280
#define D_STR_  512
#define EMB_    1792
#define EMB2_   2564
#define M_      (B_ * K_)
#define NCHUNK_ 44
#define KP1     1792
#define KP2     2624
#define NP_R21  2816
#define NB_BUILD (B_ * (K_ + 1))   // 12288

#define GBM 128
#define GBN 128
#define GSTAGES 3
#define HS 72
#define GA_BUF (GBM * HS)
#define GB_BUF (GBN * HS)
#define GSMEM_BYTES (GSTAGES * (GA_BUF + GB_BUF) * 2)   // 110592

__device__ float  g_X [(size_t)M_ * EMB_];
__device__ __half g_Y [(size_t)M_ * KP2];
__device__ __half g_XA[(size_t)M_ * KP1];
__device__ __half g_XB[(size_t)M_ * KP1];
__device__ __half g_KA[(size_t)B_ * D_SEQ_];
__device__ __half g_KB[(size_t)B_ * D_SEQ_];
__device__ float  g_P1[(size_t)M_ * D_SEQ_];
__device__ float  g_P2[(size_t)M_ * D_SEQ_];
__device__ __half g_Wt[21905408];
__device__ float  g_kin[(size_t)B_ * D_SEQ_];
__device__ float  g_Qg[(size_t)B_ * D_SEQ_];
__device__ float  g_Qr[(size_t)B_ * EMB2_];
__device__ float  g_Tg[21 * D_SEQ_];
__device__ float  g_Tr[21 * EMB2_];
__device__ int    g_cnt[21];
__device__ float  g_psum [NCHUNK_ * EMB_];
__device__ float  g_psq  [NCHUNK_ * EMB_];
__device__ float  g_psumK[4 * D_SEQ_];
__device__ float  g_psqK [4 * D_SEQ_];
__device__ float  g_ss  [8 * EMB2_];

__constant__ float c_props[21 * 4] = {
    0,0,0,0,  1,0,0,0,  0,0,0,0,  0,0,0,0,  1,0,0,0,  0,0,0,0,  0,0,0,0,
    1,0,0,0,  1,0,0,0,  0,0,0,0,  0,0,1,0,  0,0,0,0,  0,0,0,1,  0,0,1,0,
    1,0,0,0,  0,0,0,1,  0,1,0,0,  0,0,0,1,  0,1,0,0,  0,1,0,0,  0,0,0,0
};

__device__ __forceinline__ float sigmoidf_(float x) { return 1.f / (1.f + expf(-x)); }

__device__ __forceinline__ void mma_f16(float* d, const unsigned* a, const unsigned* b) {
    asm volatile(
        "mma.sync.aligned.m16n8k16.row.col.f32.f16.f16.f32 "
        "{%0,%1,%2,%3}, {%4,%5,%6,%7}, {%8,%9}, {%0,%1,%2,%3};\n"
        : "+f"(d[0]), "+f"(d[1]), "+f"(d[2]), "+f"(d[3])
        : "r"(a[0]), "r"(a[1]), "r"(a[2]), "r"(a[3]), "r"(b[0]), "r"(b[1]));
}
__device__ __forceinline__ void cp16u(unsigned dst, const void* src) {
    asm volatile("cp.async.cg.shared.global [%0], [%1], 16;\n" :: "r"(dst), "l"(src));
}
__device__ __forceinline__ void ldm4(unsigned& r0, unsigned& r1, unsigned& r2, unsigned& r3,
                                     unsigned addr) {
    asm volatile("ldmatrix.sync.aligned.m8n8.x4.shared.b16 {%0,%1,%2,%3}, [%4];"
                 : "=r"(r0), "=r"(r1), "=r"(r2), "=r"(r3) : "r"(addr));
}

// ---- prep: heavy build/kin blocks FIRST, weight transpose after ----
__global__ __launch_bounds__(256) void prep_kernel(
    const float* __restrict__ W0, const float* __restrict__ W1, const float* __restrict__ W2,
    const float* __restrict__ W3, const float* __restrict__ W4, const float* __restrict__ W5,
    __half* __restrict__ D0, __half* __restrict__ D1, __half* __restrict__ D2,
    __half* __restrict__ D3, __half* __restrict__ D4, __half* __restrict__ D5,
    const float* __restrict__ kin_in, const float* __restrict__ sub,
    const float* __restrict__ n2, const float* __restrict__ phos,
    const int* __restrict__ position,
    float* __restrict__ kin_out, float* __restrict__ X, float* __restrict__ node_feature) {
    __shared__ float t[32][33];
    int bx = blockIdx.x;
    if (bx < NB_BUILD) {
        int b = bx / (K_ + 1), k = bx % (K_ + 1);
        if (k == K_) {
            const float* base = kin_in + ((size_t)b * L_KIN_ + 1) * D_SEQ_;
            for (int i = threadIdx.x; i < D_SEQ_ / 4; i += blockDim.x) {
                float4 acc = make_float4(0.f, 0.f, 0.f, 0.f);
                #pragma unroll 8
                for (int r = 0; r < L_KIN_ - 1; ++r) {
                    float4 v = *(const float4*)(base + (size_t)r * D_SEQ_ + i * 4);
                    acc.x += v.x; acc.y += v.y; acc.z += v.z; acc.w += v.w;
                }
                const float inv = 1.f / 127.f;
                *(float4*)(kin_out + (size_t)b * D_SEQ_ + i * 4) =
                    make_float4(acc.x * inv, acc.y * inv, acc.z * inv, acc.w * inv);
            }
            return;
        }
        size_t m = (size_t)b * K_ + k;
        const float* src1 = sub + ((size_t)b * L_SUB_ + 1 + k) * D_SEQ_;
        float* dst = X + m * EMB_;
        float* nf  = node_feature + m * D_SEQ_;
        bool mid = (k == K_ / 2);
        for (int i = threadIdx.x; i < D_SEQ_ / 4; i += blockDim.x) {
            float4 v = *(const float4*)(src1 + i * 4);
            *(float4*)(nf + i * 4) = v;
            if (mid) {
                float4 p = *(const float4*)(phos + i * 4);
                v.x += p.x; v.y += p.y; v.z += p.z; v.w += p.w;
            }
            *(float4*)(dst + i * 4) = v;
        }
        int row = position[b] + k - K_ / 2;
        bool ok = (row >= 0 && row < L_STR_);
        const float* src2 = n2 + ((size_t)b * L_STR_ + (ok ? row : 0)) * D_STR_;
        for (int i = threadIdx.x; i < D_STR_ / 4; i += blockDim.x) {
            float4 v = make_float4(0.f, 0.f, 0.f, 0.f);
            if (ok) v = *(const float4*)(src2 + i * 4);
            if (mid) {
                float4 p = *(const float4*)(phos + D_SEQ_ + i * 4);
                v.x += p.x; v.y += p.y; v.z += p.z; v.w += p.w;
            }
            *(float4*)(dst + D_SEQ_ + i * 4) = v;
        }
        return;
    }
    bx -= NB_BUILD;
    const float* W; __half* D; int K, N, KP, kb, blk;
    if      (bx < 2240)  { W=W0; D=D0; K=EMB_;  N=1280;  KP=KP1; kb=56; blk=bx; }
    else if (bx < 5376)  { W=W1; D=D1; K=EMB_;  N=1792;  KP=KP1; kb=56; blk=bx-2240; }
    else if (bx < 7616)  { W=W2; D=D2; K=EMB_;  N=1280;  KP=KP1; kb=56; blk=bx-5376; }
    else if (bx < 10896) { W=W3; D=D3; K=EMB2_; N=1280;  KP=KP2; kb=82; blk=bx-7616; }
    else if (bx < 18112) { W=W4; D=D4; K=EMB2_; N=EMB2_; KP=KP2; kb=82; blk=bx-10896; }
    else                 { W=W5; D=D5; K=EMB2_; N=1280;  KP=KP2; kb=82; blk=bx-18112; }
    int k0 = (blk % kb) * 32, n0 = (blk / kb) * 32;
    int tx = threadIdx.x & 31, ty = threadIdx.x >> 5;
    #pragma unroll
    for (int j = 0; j < 4; ++j) {
        int k = k0 + ty + j * 8, n = n0 + tx;
        t[ty + j * 8][tx] = (k < K && n < N) ? W[(size_t)k * N + n] : 0.f;
    }
    __syncthreads();
    #pragma unroll
    for (int j = 0; j < 4; ++j) {
        int n = n0 + ty + j * 8, k = k0 + tx;
        D[(size_t)n * KP + k] = __float2half(t[tx][ty + j * 8]);
    }
}

__global__ __launch_bounds__(256) void colstats_partial(
    const float* __restrict__ X, float* __restrict__ psum, float* __restrict__ psq,
    int ncols, int rows_per_chunk) {
    int col = blockIdx.x * blockDim.x + threadIdx.x;
    if (col >= ncols) return;
    int r0 = blockIdx.y * rows_per_chunk;
    float s = 0.f, q = 0.f;
    const float* p = X + (size_t)r0 * ncols + col;
    #pragma unroll 8
    for (int r = 0; r < rows_per_chunk; ++r, p += ncols) {
        float v = *p;
        s += v; q += v * v;
    }
    psum[blockIdx.y * ncols + col] = s;
    psq [blockIdx.y * ncols + col] = q;
}

__global__ __launch_bounds__(256) void finalize_stats(
    const float* __restrict__ psum, const float* __restrict__ psq, int ncols,
    const float* __restrict__ gA, const float* __restrict__ bA,
    const float* __restrict__ gB, const float* __restrict__ bB,
    float* __restrict__ sA, float* __restrict__ tA,
    float* __restrict__ sB, float* __restrict__ tB) {
    int col = blockIdx.x * blockDim.x + threadIdx.x;
    if (col >= ncols) return;
    float s = 0.f, q = 0.f;
    for (int c = 0; c < NCHUNK_; ++c) {
        s += psum[c * ncols + col];
        q += psq [c * ncols + col];
    }
    const float inv_n = 1.f / (float)M_;
    float mean = s * inv_n;
    float var  = q * inv_n - mean * mean;
    float inv  = rsqrtf(var + 1e-5f);
    float sa = gA[col] * inv; sA[col] = sa; tA[col] = bA[col] - mean * sa;
    float sb = gB[col] * inv; sB[col] = sb; tB[col] = bB[col] - mean * sb;
}

__global__ __launch_bounds__(256) void stats2_kernel(
    const float* __restrict__ X2, const float* __restrict__ kin, const int* __restrict__ seq,
    float* __restrict__ psum, float* __restrict__ psq,
    float* __restrict__ psumK, float* __restrict__ psqK, int* __restrict__ cnt) {
    int bx = blockIdx.x;
    if (bx < 220) {
        int col = (bx % 5) * 256 + threadIdx.x;
        int chunk = bx / 5;
        float s = 0.f, q = 0.f;
        const float* p = X2 + (size_t)chunk * 256 * D_SEQ_ + col;
        #pragma unroll 8
        for (int r = 0; r < 256; ++r, p += D_SEQ_) { float v = *p; s += v; q += v * v; }
        psum[chunk * D_SEQ_ + col] = s;
        psq [chunk * D_SEQ_ + col] = q;
    } else if (bx < 240) {
        int b2 = bx - 220;
        int col = (b2 % 5) * 256 + threadIdx.x;
        int chunk = b2 / 5;
        float s = 0.f, q = 0.f;
        const float* p = kin + (size_t)chunk * 256 * D_SEQ_ + col;
        #pragma unroll 8
        for (int r = 0; r < 256; ++r, p += D_SEQ_) { float v = *p; s += v; q += v * v; }
        psumK[chunk * D_SEQ_ + col] = s;
        psqK [chunk * D_SEQ_ + col] = q;
    } else {
        __shared__ int h[21];
        if (threadIdx.x < 21) h[threadIdx.x] = 0;
        __syncthreads();
        for (int i = threadIdx.x; i < M_; i += blockDim.x) atomicAdd(&h[seq[i]], 1);
        __syncthreads();
        if (threadIdx.x < 21) cnt[threadIdx.x] = h[threadIdx.x];
    }
}

__global__ __launch_bounds__(256) void finalize_stats2(
    const float* __restrict__ psum, const float* __restrict__ psq,
    const float* __restrict__ psumK, const float* __restrict__ psqK,
    const int* __restrict__ cnt,
    const float* __restrict__ gA, const float* __restrict__ bA,
    const float* __restrict__ gB, const float* __restrict__ bB,
    float* __restrict__ sA, float* __restrict__ tA,
    float* __restrict__ sB, float* __restrict__ tB) {
    int col = blockIdx.x * blockDim.x + threadIdx.x;
    if (col >= EMB2_) return;
    float mean, var;
    if (col < D_SEQ_) {
        float s = 0.f, q = 0.f;
        for (int c = 0; c < NCHUNK_; ++c) { s += psum[c * D_SEQ_ + col]; q += psq[c * D_SEQ_ + col]; }
        mean = s / (float)M_; var = q / (float)M_ - mean * mean;
    } else if (col < 2 * D_SEQ_) {
        int j = col - D_SEQ_;
        float s = 0.f, q = 0.f;
        for (int c = 0; c < 4; ++c) { s += psumK[c * D_SEQ_ + j]; q += psqK[c * D_SEQ_ + j]; }
        mean = s / (float)B_; var = q / (float)B_ - mean * mean;
    } else {
        int j = col - 2 * D_SEQ_;
        float s = 0.f;
        for (int sd = 0; sd < 21; ++sd) s += (float)cnt[sd] * c_props[sd * 4 + j];
        mean = s / (float)M_; var = mean - mean * mean;
    }
    float inv = rsqrtf(var + 1e-5f);
    float sa = gA[col] * inv; sA[col] = sa; tA[col] = bA[col] - mean * sa;
    float sb = gB[col] * inv; sB[col] = sb; tB[col] = bB[col] - mean * sb;
}

__global__ __launch_bounds__(256) void props_merged(
    const float* __restrict__ Wg, const float* __restrict__ Wr,
    const float* __restrict__ sg, const float* __restrict__ tg,
    const float* __restrict__ sr, const float* __restrict__ tr,
    float* __restrict__ Tg, float* __restrict__ Tr) {
    int idx = blockIdx.x * blockDim.x + threadIdx.x;
    const float* W; const float* s; const float* t; float* T; int N; int i;
    if (idx < 21 * 1280) { W = Wg; s = sg; t = tg; T = Tg; N = 1280; i = idx; }
    else {
        i = idx - 21 * 1280;
        if (i >= 21 * EMB2_) return;
        W = Wr; s = sr; t = tr; T = Tr; N = EMB2_;
    }
    int sid = i / N, n = i % N;
    float acc = 0.f;
    #pragma unroll
    for (int j = 0; j < 4; ++j) {
        float pv = fmaxf(fmaf(c_props[sid * 4 + j], s[j], t[j]), 0.f);
        acc += pv * W[(size_t)(2 * D_SEQ_ + j) * N + n];
    }
    T[i] = acc;
}

__global__ __launch_bounds__(256) void bn_transform_kernel(
    const float* __restrict__ X,
    const float* __restrict__ s1, const float* __restrict__ t1,
    const float* __restrict__ s2, const float* __restrict__ t2,
    __half* __restrict__ XA, __half* __restrict__ XB, int ncols, int ldo, int nj) {
    int j = blockIdx.x * blockDim.x + threadIdx.x;
    if (j >= nj) return;
    int row = blockIdx.y;
    int c = j * 2;
    const float* xr = X + (size_t)row * ncols;
    float a0 = 0.f, a1 = 0.f, b0 = 0.f, b1 = 0.f;
    if (c < ncols) {
        float v0 = xr[c], v1 = xr[c + 1];
        a0 = fmaxf(fmaf(v0, s1[c], t1[c]), 0.f);
        a1 = fmaxf(fmaf(v1, s1[c + 1], t1[c + 1]), 0.f);
        b0 = fmaxf(fmaf(v0, s2[c], t2[c]), 0.f);
        b1 = fmaxf(fmaf(v1, s2[c + 1], t2[c + 1]), 0.f);
    }
    size_t o = (size_t)row * ldo + c;
    *(__half2*)(XA + o) = __floats2half2_rn(a0, a1);
    *(__half2*)(XB + o) = __floats2half2_rn(b0, b1);
}

__global__ __launch_bounds__(256) void bn2_kernel(
    const float* __restrict__ X2, const float* __restrict__ kin, const float* __restrict__ ss) {
    int j = blockIdx.x * blockDim.x + threadIdx.x;
    if (j >= D_SEQ_ / 2) return;
    int row = blockIdx.y;
    const float* s1; const float* t1; const float* s2; const float* t2;
    const float* xr; __half* oA; __half* oB; size_t orow;
    if (row < M_) {
        s1 = ss + 4 * EMB2_;  t1 = ss + 5 * EMB2_;
        s2 = ss + 6 * EMB2_;  t2 = ss + 7 * EMB2_;
        xr = X2 + (size_t)row * D_SEQ_;
        oA = g_XA; oB = g_XB; orow = (size_t)row * D_SEQ_;
    } else {
        int rb = row - M_;
        s1 = ss + 4 * EMB2_ + D_SEQ_;  t1 = ss + 5 * EMB2_ + D_SEQ_;
        s2 = ss + 6 * EMB2_ + D_SEQ_;  t2 = ss + 7 * EMB2_ + D_SEQ_;
        xr = kin + (size_t)rb * D_SEQ_;
        oA = g_KA; oB = g_KB; orow = (size_t)rb * D_SEQ_;
    }
    int c = j * 2;
    float v0 = xr[c], v1 = xr[c + 1];
    float a0 = fmaxf(fmaf(v0, s1[c], t1[c]), 0.f);
    float a1 = fmaxf(fmaf(v1, s1[c + 1], t1[c + 1]), 0.f);
    float b0 = fmaxf(fmaf(v0, s2[c], t2[c]), 0.f);
    float b1 = fmaxf(fmaf(v1, s2[c + 1], t2[c + 1]), 0.f);
    *(__half2*)(oA + orow + c) = __floats2half2_rn(a0, a1);
    *(__half2*)(oB + orow + c) = __floats2half2_rn(b0, b1);
}

// ---- GEMM parameter bundle (passed by value) ----
struct GemmArgs {
    const __half* A; const __half* Wt;
    const float* bias; float* Cf; __half* Ch;
    int lda, ldw, ktiles, Nout, Nzero, ldc;
    const float* Q; int ldq;
    const float* T; int ldt; const int* seq;
    const float* Pg; const float* NF; const float* avec;
    int gn;   // grid width in N-tiles
};

// ---- fp16 GEMM body: 128x128x64, 8 warps of 64x32, 3-stage, ldmatrix ----
__device__ __forceinline__ void gemm_body(const GemmArgs& P, int bxn, int bym) {
    extern __shared__ __half smh[];
    const unsigned sA_u = (unsigned)__cvta_generic_to_shared(smh);
    const unsigned sB_u = sA_u + (unsigned)(GSTAGES * GA_BUF) * 2u;

    const int tid  = threadIdx.x;
    const int bm   = bym * GBM;
    const int bn   = bxn * GBN;
    const int warp = tid >> 5, lane = tid & 31;
    const int wm = (warp & 1) << 6;
    const int wn = (warp >> 1) << 5;
    const int g  = lane >> 2, tg = lane & 3;

    const int t    = lane >> 3;
    const int a_m  = ((t & 1) << 3) + (lane & 7);
    const int a_ko = (t >> 1) << 3;
    const int b_n  = ((t >> 1) << 3) + (lane & 7);
    const int b_ko = (t & 1) << 3;

    float acc[4][4][4];
    #pragma unroll
    for (int mt = 0; mt < 4; ++mt)
        #pragma unroll
        for (int nt = 0; nt < 4; ++nt)
            #pragma unroll
            for (int i = 0; i < 4; ++i) acc[mt][nt][i] = 0.f;

    auto load_stage = [&](int kt, int buf) {
        const int k0 = kt * 64;
        unsigned sab = sA_u + (unsigned)(buf * GA_BUF) * 2u;
        #pragma unroll
        for (int it = 0; it < 4; ++it) {
            int idx = tid + it * 256;
            int row = idx >> 3, seg = idx & 7;
            cp16u(sab + (unsigned)(row * HS + seg * 8) * 2u,
                  P.A + (size_t)(bm + row) * P.lda + k0 + seg * 8);
        }
        unsigned sbb = sB_u + (unsigned)(buf * GB_BUF) * 2u;
        #pragma unroll
        for (int it = 0; it < 4; ++it) {
            int idx = tid + it * 256;
            int row = idx >> 3, seg = idx & 7;
            cp16u(sbb + (unsigned)(row * HS + seg * 8) * 2u,
                  P.Wt + (size_t)(bn + row) * P.ldw + k0 + seg * 8);
        }
        asm volatile("cp.async.commit_group;\n");
    };

    auto compute = [&](int buf) {
        const unsigned pA = sA_u + (unsigned)(buf * GA_BUF) * 2u;
        const unsigned pB = sB_u + (unsigned)(buf * GB_BUF) * 2u;
        #pragma unroll
        for (int kk = 0; kk < 4; ++kk) {
            unsigned af[4][4], bf[4][2];
            #pragma unroll
            for (int mt = 0; mt < 4; ++mt) {
                unsigned addr = pA + (unsigned)(((wm + (mt << 4) + a_m) * HS
                                                + (kk << 4) + a_ko) << 1);
                ldm4(af[mt][0], af[mt][1], af[mt][2], af[mt][3], addr);
            }
            #pragma unroll
            for (int p = 0; p < 2; ++p) {
                unsigned addr = pB + (unsigned)(((wn + (p << 4) + b_n) * HS
                                                + (kk << 4) + b_ko) << 1);
                ldm4(bf[2*p][0], bf[2*p][1], bf[2*p+1][0], bf[2*p+1][1], addr);
            }
            #pragma unroll
            for (int mt = 0; mt < 4; ++mt)
                #pragma unroll
                for (int nt = 0; nt < 4; ++nt)
                    mma_f16(acc[mt][nt], af[mt], bf[nt]);
        }
    };

    #pragma unroll
    for (int s = 0; s < GSTAGES - 1; ++s) load_stage(s, s);

    for (int kt = 0; kt < P.ktiles; ++kt) {
        asm volatile("cp.async.wait_group %0;\n" :: "n"(GSTAGES - 2));
        __syncthreads();
        int nxt = kt + GSTAGES - 1;
        if (nxt < P.ktiles) load_stage(nxt, nxt % GSTAGES);
        else asm volatile("cp.async.commit_group;\n");
        compute(kt % GSTAGES);
    }

    float ca0 = 0.f, ca1 = 0.f;
    if (P.avec) { ca0 = P.avec[0]; ca1 = P.avec[1]; }

    #pragma unroll
    for (int mt = 0; mt < 4; ++mt) {
        int r = bm + wm + (mt << 4);
        int m0 = r + g, m1 = r + g + 8;
        const float* q0 = P.Q ? P.Q + (size_t)(m0 / 11) * P.ldq : nullptr;
        const float* q1 = P.Q ? P.Q + (size_t)(m1 / 11) * P.ldq : nullptr;
        const float* t0 = P.T ? P.T + (size_t)P.seq[m0] * P.ldt : nullptr;
        const float* t1p = P.T ? P.T + (size_t)P.seq[m1] * P.ldt : nullptr;
        #pragma unroll
        for (int nt = 0; nt < 4; ++nt) {
            int c = bn + wn + (nt << 3) + (tg << 1);
            #pragma unroll
            for (int half = 0; half < 2; ++half) {
                int cc = c + half;
                if (cc >= P.Nzero) continue;
                float v0 = 0.f, v1 = 0.f;
                if (cc < P.Nout) {
                    float bb = P.bias ? P.bias[cc] : 0.f;
                    v0 = acc[mt][nt][half]     + bb;
                    v1 = acc[mt][nt][half + 2] + bb;
                    if (q0) { v0 += q0[cc]; v1 += q1[cc]; }
                    if (t0) { v0 += t0[cc]; v1 += t1p[cc]; }
                }
                if (P.avec) {
                    float p0 = P.Pg[(size_t)m0 * P.ldc + cc], n0v = P.NF[(size_t)m0 * P.ldc + cc];
                    float p1 = P.Pg[(size_t)m1 * P.ldc + cc], n1v = P.NF[(size_t)m1 * P.ldc + cc];
                    P.Cf[(size_t)m0 * P.ldc + cc] = sigmoidf_(p0) * n0v * ca0 + v0 * ca1;
                    P.Cf[(size_t)m1 * P.ldc + cc] = sigmoidf_(p1) * n1v * ca0 + v1 * ca1;
                } else if (P.Ch) {
                    P.Ch[(size_t)m0 * P.ldc + cc] = __float2half(fmaxf(v0, 0.f));
                    P.Ch[(size_t)m1 * P.ldc + cc] = __float2half(fmaxf(v1, 0.f));
                } else if (cc < P.Nout) {
                    P.Cf[(size_t)m0 * P.ldc + cc] = v0;
                    P.Cf[(size_t)m1 * P.ldc + cc] = v1;
                }
            }
        }
    }
}

__global__ __launch_bounds__(256, 2) void gemm_single(GemmArgs P) {
    gemm_body(P, blockIdx.x, blockIdx.y);
}
__global__ __launch_bounds__(256, 2) void gemm_dual(GemmArgs Pa, GemmArgs Pb, int na) {
    int i = blockIdx.x;
    if (i < na) gemm_body(Pa, i % Pa.gn, i / Pa.gn);
    else { i -= na; gemm_body(Pb, i % Pb.gn, i / Pb.gn); }
}

__global__ __launch_bounds__(256) void final_kernel(
    const float* __restrict__ G1, const float* __restrict__ G2,
    const float* __restrict__ X2, const float* __restrict__ a2,
    float* __restrict__ out) {
    int b = blockIdx.x;
    float s0 = a2[0], s1 = a2[1];
    for (int i = threadIdx.x; i < D_SEQ_ / 4; i += blockDim.x) {
        float4 acc = make_float4(0.f, 0.f, 0.f, 0.f);
        for (int k = 0; k < K_; ++k) {
            size_t m = (size_t)b * K_ + k;
            float4 f1 = *(const float4*)(G1 + m * D_SEQ_ + i * 4);
            float4 f2 = *(const float4*)(G2 + m * D_SEQ_ + i * 4);
            float4 gn = *(const float4*)(X2 + m * D_SEQ_ + i * 4);
            acc.x += sigmoidf_(f1.x) * gn.x * s0 + f2.x * s1;
            acc.y += sigmoidf_(f1.y) * gn.y * s0 + f2.y * s1;
            acc.z += sigmoidf_(f1.z) * gn.z * s0 + f2.z * s1;
            acc.w += sigmoidf_(f1.w) * gn.w * s0 + f2.w * s1;
        }
        *(float4*)(out + (size_t)b * D_SEQ_ + i * 4) = acc;
    }
}

static GemmArgs mk(const __half* A, const __half* Wt, const float* bias,
                   float* Cf, __half* Ch, int lda, int ldw, int ktiles,
                   int Nout, int Nzero, int ldc,
                   const float* Q, int ldq, const float* T, int ldt, const int* seq,
                   const float* Pg, const float* NF, const float* avec, int gn) {
    GemmArgs p;
    p.A = A; p.Wt = Wt; p.bias = bias; p.Cf = Cf; p.Ch = Ch;
    p.lda = lda; p.ldw = ldw; p.ktiles = ktiles;
    p.Nout = Nout; p.Nzero = Nzero; p.ldc = ldc;
    p.Q = Q; p.ldq = ldq; p.T = T; p.ldt = ldt; p.seq = seq;
    p.Pg = Pg; p.NF = NF; p.avec = avec; p.gn = gn;
    return p;
}

extern "C" void kernel_launch(void* const* d_in, const int* in_sizes, int n_in,
                              void* d_out, int out_size) {
    const float* kin_in   = (const float*)d_in[0];
    const float* sub      = (const float*)d_in[1];
    const float* n2       = (const float*)d_in[2];
    const float* a        = (const float*)d_in[4];
    const float* a2       = (const float*)d_in[5];
    const float* phos     = (const float*)d_in[6];
    const float* g1_gamma = (const float*)d_in[7];
    const float* g1_beta  = (const float*)d_in[8];
    const float* g1_W     = (const float*)d_in[9];
    const float* g1_b     = (const float*)d_in[10];
    const float* r1_gamma = (const float*)d_in[11];
    const float* r1_beta  = (const float*)d_in[12];
    const float* r1_W1    = (const float*)d_in[13];
    const float* r1_b1    = (const float*)d_in[14];
    const float* r1_W2    = (const float*)d_in[15];
    const float* r1_b2    = (const float*)d_in[16];
    const float* g2_gamma = (const float*)d_in[17];
    const float* g2_beta  = (const float*)d_in[18];
    const float* g2_W     = (const float*)d_in[19];
    const float* g2_b     = (const float*)d_in[20];
    const float* r2_gamma = (const float*)d_in[21];
    const float* r2_beta  = (const float*)d_in[22];
    const float* r2_W1    = (const float*)d_in[23];
    const float* r2_b1    = (const float*)d_in[24];
    const float* r2_W2    = (const float*)d_in[25];
    const float* r2_b2    = (const float*)d_in[26];
    const int*   position = (const int*)d_in[27];
    const int*   raw_seq  = (const int*)d_in[28];

    float* out = (float*)d_out;
    float* graph_feature = out;
    float* node_feature  = out + (size_t)B_ * D_SEQ_;

    float *X, *P1, *P2, *kin, *Qg, *Qr, *Tg, *Tr, *psum, *psq, *psumK, *psqK, *ss;
    int* cnt;
    __half *Y, *XA, *XB, *KA, *KB, *Wt;
    cudaGetSymbolAddress((void**)&X,     g_X);
    cudaGetSymbolAddress((void**)&Y,     g_Y);
    cudaGetSymbolAddress((void**)&XA,    g_XA);
    cudaGetSymbolAddress((void**)&XB,    g_XB);
    cudaGetSymbolAddress((void**)&KA,    g_KA);
    cudaGetSymbolAddress((void**)&KB,    g_KB);
    cudaGetSymbolAddress((void**)&P1,    g_P1);
    cudaGetSymbolAddress((void**)&P2,    g_P2);
    cudaGetSymbolAddress((void**)&Wt,    g_Wt);
    cudaGetSymbolAddress((void**)&kin,   g_kin);
    cudaGetSymbolAddress((void**)&Qg,    g_Qg);
    cudaGetSymbolAddress((void**)&Qr,    g_Qr);
    cudaGetSymbolAddress((void**)&Tg,    g_Tg);
    cudaGetSymbolAddress((void**)&Tr,    g_Tr);
    cudaGetSymbolAddress((void**)&cnt,   g_cnt);
    cudaGetSymbolAddress((void**)&psum,  g_psum);
    cudaGetSymbolAddress((void**)&psq,   g_psq);
    cudaGetSymbolAddress((void**)&psumK, g_psumK);
    cudaGetSymbolAddress((void**)&psqK,  g_psqK);
    cudaGetSymbolAddress((void**)&ss,    g_ss);

    cudaFuncSetAttribute(gemm_single, cudaFuncAttributeMaxDynamicSharedMemorySize, GSMEM_BYTES);
    cudaFuncSetAttribute(gemm_dual,   cudaFuncAttributeMaxDynamicSharedMemorySize, GSMEM_BYTES);

    float* s_g1 = ss + 0 * EMB2_;  float* t_g1 = ss + 1 * EMB2_;
    float* s_r1 = ss + 2 * EMB2_;  float* t_r1 = ss + 3 * EMB2_;
    float* s_g2 = ss + 4 * EMB2_;  float* t_g2 = ss + 5 * EMB2_;
    float* s_r2 = ss + 6 * EMB2_;  float* t_r2 = ss + 7 * EMB2_;

    __half* Wt_g1  = Wt;
    __half* Wt_r11 = Wt_g1  + (size_t)1280 * KP1;
    __half* Wt_r12 = Wt_r11 + (size_t)1792 * KP1;
    __half* Wt_g2  = Wt_r12 + (size_t)1280 * KP1;
    __half* Wt_r21 = Wt_g2  + (size_t)1280 * KP2;
    __half* Wt_r22 = Wt_r21 + (size_t)NP_R21 * KP2;

    prep_kernel<<<NB_BUILD + 21392, 256>>>(
        g1_W, r1_W1, r1_W2, g2_W, r2_W1, r2_W2,
        Wt_g1, Wt_r11, Wt_r12, Wt_g2, Wt_r21, Wt_r22,
        kin_in, sub, n2, phos, position, kin, X, node_feature);

    colstats_partial<<<dim3((EMB_ + 255) / 256, NCHUNK_), 256>>>(X, psum, psq, EMB_, M_ / NCHUNK_);
    finalize_stats<<<(EMB_ + 255) / 256, 256>>>(psum, psq, EMB_,
        g1_gamma, g1_beta, r1_gamma, r1_beta, s_g1, t_g1, s_r1, t_r1);
    bn_transform_kernel<<<dim3((KP1 / 2 + 255) / 256, M_), 256>>>(
        X, s_g1, t_g1, s_r1, t_r1, XA, XB, EMB_, KP1, KP1 / 2);

    // stage-1: r11 (larger) + g1 merged; then r12 with fused combine -> X2
    {
        GemmArgs pr11 = mk(XB, Wt_r11, r1_b1, nullptr, Y, KP1, KP1, 28, 1792, 1792, KP1,
                           nullptr, 0, nullptr, 0, nullptr, nullptr, nullptr, nullptr, 14);
        GemmArgs pg1  = mk(XA, Wt_g1,  g1_b,  P1, nullptr, KP1, KP1, 28, 1280, 1280, 1280,
                           nullptr, 0, nullptr, 0, nullptr, nullptr, nullptr, nullptr, 10);
        gemm_dual<<<14 * 88 + 10 * 88, 256, GSMEM_BYTES>>>(pr11, pg1, 14 * 88);
    }
    {
        GemmArgs pr12 = mk(Y, Wt_r12, r1_b2, X, nullptr, KP1, KP1, 28, 1280, 1280, 1280,
                           nullptr, 0, nullptr, 0, nullptr, P1, node_feature, a, 10);
        gemm_single<<<dim3(10, 88), 256, GSMEM_BYTES>>>(pr12);
    }

    stats2_kernel<<<241, 256>>>(X, kin, raw_seq, psum, psq, psumK, psqK, cnt);
    finalize_stats2<<<(EMB2_ + 255) / 256, 256>>>(psum, psq, psumK, psqK, cnt,
        g2_gamma, g2_beta, r2_gamma, r2_beta, s_g2, t_g2, s_r2, t_r2);

    bn2_kernel<<<dim3(3, M_ + B_), 256>>>(X, kin, ss);
    props_merged<<<(21 * (1280 + EMB2_) + 255) / 256, 256>>>(
        g2_W, r2_W1, s_g2 + 2 * D_SEQ_, t_g2 + 2 * D_SEQ_,
        s_r2 + 2 * D_SEQ_, t_r2 + 2 * D_SEQ_, Tg, Tr);

    // kin GEMMs merged (Qr larger first)
    {
        GemmArgs pqr = mk(KB, Wt_r21 + 1280, nullptr, Qr, nullptr, D_SEQ_, KP2, 20,
                          EMB2_, EMB2_, EMB2_, nullptr, 0, nullptr, 0, nullptr,
                          nullptr, nullptr, nullptr, 21);
        GemmArgs pqg = mk(KA, Wt_g2 + 1280, nullptr, Qg, nullptr, D_SEQ_, KP2, 20,
                          1280, 1280, 1280, nullptr, 0, nullptr, 0, nullptr,
                          nullptr, nullptr, nullptr, 10);
        gemm_dual<<<21 * 8 + 10 * 8, 256, GSMEM_BYTES>>>(pqr, pqg, 21 * 8);
    }

    // stage-2 main GEMMs merged (r21 larger first), then r22
    {
        GemmArgs pr21 = mk(XB, Wt_r21, r2_b1, nullptr, Y, D_SEQ_, KP2, 20, EMB2_, KP2, KP2,
                           Qr, EMB2_, Tr, EMB2_, raw_seq, nullptr, nullptr, nullptr, 21);
        GemmArgs pg2  = mk(XA, Wt_g2,  g2_b,  P1, nullptr, D_SEQ_, KP2, 20, 1280, 1280, 1280,
                           Qg, 1280, Tg, 1280, raw_seq, nullptr, nullptr, nullptr, 10);
        gemm_dual<<<21 * 88 + 10 * 88, 256, GSMEM_BYTES>>>(pr21, pg2, 21 * 88);
    }
    {
        GemmArgs pr22 = mk(Y, Wt_r22, r2_b2, P2, nullptr, KP2, KP2, 41, 1280, 1280, 1280,
                           nullptr, 0, nullptr, 0, nullptr, nullptr, nullptr, nullptr, 10);
        gemm_single<<<dim3(10, 88), 256, GSMEM_BYTES>>>(pr22);
    }

    final_kernel<<<B_, 256>>>(P1, P2, X, a2, graph_feature);
}

// round 15
// speedup vs baseline: 1.1629x; 1.0020x over previous
#include <cuda_runtime.h>
#include <cuda_fp16.h>
#include <cstdint>

#define B_      1024
#define K_      11
#define L_KIN_  128
#define L_SUB_  64
#define L_STR_  128
#define D_SEQ_  1280
#define D_STR_  512
#define EMB_    1792
#define EMB2_   2564
#define M_      (B_ * K_)
#define NCHUNK_ 44
#define KP1     1792
#define KP2     2624
#define NP_R21  2816
#define NB_BUILD (B_ * (K_ + 1))
#define NPROPS  (21 * (D_SEQ_ + EMB2_))   // 80724

#define GBM 128
#define GBN 128
#define GSTAGES 3
#define HS 72
#define GA_BUF (GBM * HS)
#define GB_BUF (GBN * HS)
#define GSMEM_BYTES (GSTAGES * (GA_BUF + GB_BUF) * 2)   // 110592

__device__ float  g_X [(size_t)M_ * EMB_];
__device__ __half g_Y [(size_t)M_ * KP2];
__device__ __half g_XA[(size_t)M_ * KP1];
__device__ __half g_XB[(size_t)M_ * KP1];
__device__ __half g_KA[(size_t)B_ * D_SEQ_];
__device__ __half g_KB[(size_t)B_ * D_SEQ_];
__device__ float  g_P1[(size_t)M_ * D_SEQ_];
__device__ float  g_P2[(size_t)M_ * D_SEQ_];
__device__ __half g_Wt[21905408];
__device__ float  g_kin[(size_t)B_ * D_SEQ_];
__device__ float  g_Qg[(size_t)B_ * D_SEQ_];
__device__ float  g_Qr[(size_t)B_ * EMB2_];
__device__ float  g_Tg[21 * D_SEQ_];
__device__ float  g_Tr[21 * EMB2_];
__device__ int    g_cnt[21];
__device__ float  g_psum [NCHUNK_ * EMB_];
__device__ float  g_psq  [NCHUNK_ * EMB_];
__device__ float  g_psumK[4 * D_SEQ_];
__device__ float  g_psqK [4 * D_SEQ_];
__device__ float  g_ss  [8 * EMB2_];

__constant__ float c_props[21 * 4] = {
    0,0,0,0,  1,0,0,0,  0,0,0,0,  0,0,0,0,  1,0,0,0,  0,0,0,0,  0,0,0,0,
    1,0,0,0,  1,0,0,0,  0,0,0,0,  0,0,1,0,  0,0,0,0,  0,0,0,1,  0,0,1,0,
    1,0,0,0,  0,0,0,1,  0,1,0,0,  0,0,0,1,  0,1,0,0,  0,1,0,0,  0,0,0,0
};

__device__ __forceinline__ float sigmoidf_(float x) { return 1.f / (1.f + expf(-x)); }

__device__ __forceinline__ void mma_f16(float* d, const unsigned* a, const unsigned* b) {
    asm volatile(
        "mma.sync.aligned.m16n8k16.row.col.f32.f16.f16.f32 "
        "{%0,%1,%2,%3}, {%4,%5,%6,%7}, {%8,%9}, {%0,%1,%2,%3};\n"
        : "+f"(d[0]), "+f"(d[1]), "+f"(d[2]), "+f"(d[3])
        : "r"(a[0]), "r"(a[1]), "r"(a[2]), "r"(a[3]), "r"(b[0]), "r"(b[1]));
}
__device__ __forceinline__ void cp16u(unsigned dst, const void* src) {
    asm volatile("cp.async.cg.shared.global [%0], [%1], 16;\n" :: "r"(dst), "l"(src));
}
__device__ __forceinline__ void ldm4(unsigned& r0, unsigned& r1, unsigned& r2, unsigned& r3,
                                     unsigned addr) {
    asm volatile("ldmatrix.sync.aligned.m8n8.x4.shared.b16 {%0,%1,%2,%3}, [%4];"
                 : "=r"(r0), "=r"(r1), "=r"(r2), "=r"(r3) : "r"(addr));
}

// ---- prep: heavy build/kin blocks FIRST, weight transpose after ----
__global__ __launch_bounds__(256) void prep_kernel(
    const float* __restrict__ W0, const float* __restrict__ W1, const float* __restrict__ W2,
    const float* __restrict__ W3, const float* __restrict__ W4, const float* __restrict__ W5,
    __half* __restrict__ D0, __half* __restrict__ D1, __half* __restrict__ D2,
    __half* __restrict__ D3, __half* __restrict__ D4, __half* __restrict__ D5,
    const float* __restrict__ kin_in, const float* __restrict__ sub,
    const float* __restrict__ n2, const float* __restrict__ phos,
    const int* __restrict__ position,
    float* __restrict__ kin_out, float* __restrict__ X, float* __restrict__ node_feature) {
    __shared__ float t[32][33];
    int bx = blockIdx.x;
    if (bx < NB_BUILD) {
        int b = bx / (K_ + 1), k = bx % (K_ + 1);
        if (k == K_) {
            const float* base = kin_in + ((size_t)b * L_KIN_ + 1) * D_SEQ_;
            for (int i = threadIdx.x; i < D_SEQ_ / 4; i += blockDim.x) {
                float4 acc = make_float4(0.f, 0.f, 0.f, 0.f);
                #pragma unroll 8
                for (int r = 0; r < L_KIN_ - 1; ++r) {
                    float4 v = *(const float4*)(base + (size_t)r * D_SEQ_ + i * 4);
                    acc.x += v.x; acc.y += v.y; acc.z += v.z; acc.w += v.w;
                }
                const float inv = 1.f / 127.f;
                *(float4*)(kin_out + (size_t)b * D_SEQ_ + i * 4) =
                    make_float4(acc.x * inv, acc.y * inv, acc.z * inv, acc.w * inv);
            }
            return;
        }
        size_t m = (size_t)b * K_ + k;
        const float* src1 = sub + ((size_t)b * L_SUB_ + 1 + k) * D_SEQ_;
        float* dst = X + m * EMB_;
        float* nf  = node_feature + m * D_SEQ_;
        bool mid = (k == K_ / 2);
        for (int i = threadIdx.x; i < D_SEQ_ / 4; i += blockDim.x) {
            float4 v = *(const float4*)(src1 + i * 4);
            *(float4*)(nf + i * 4) = v;
            if (mid) {
                float4 p = *(const float4*)(phos + i * 4);
                v.x += p.x; v.y += p.y; v.z += p.z; v.w += p.w;
            }
            *(float4*)(dst + i * 4) = v;
        }
        int row = position[b] + k - K_ / 2;
        bool ok = (row >= 0 && row < L_STR_);
        const float* src2 = n2 + ((size_t)b * L_STR_ + (ok ? row : 0)) * D_STR_;
        for (int i = threadIdx.x; i < D_STR_ / 4; i += blockDim.x) {
            float4 v = make_float4(0.f, 0.f, 0.f, 0.f);
            if (ok) v = *(const float4*)(src2 + i * 4);
            if (mid) {
                float4 p = *(const float4*)(phos + D_SEQ_ + i * 4);
                v.x += p.x; v.y += p.y; v.z += p.z; v.w += p.w;
            }
            *(float4*)(dst + D_SEQ_ + i * 4) = v;
        }
        return;
    }
    bx -= NB_BUILD;
    const float* W; __half* D; int K, N, KP, kb, blk;
    if      (bx < 2240)  { W=W0; D=D0; K=EMB_;  N=1280;  KP=KP1; kb=56; blk=bx; }
    else if (bx < 5376)  { W=W1; D=D1; K=EMB_;  N=1792;  KP=KP1; kb=56; blk=bx-2240; }
    else if (bx < 7616)  { W=W2; D=D2; K=EMB_;  N=1280;  KP=KP1; kb=56; blk=bx-5376; }
    else if (bx < 10896) { W=W3; D=D3; K=EMB2_; N=1280;  KP=KP2; kb=82; blk=bx-7616; }
    else if (bx < 18112) { W=W4; D=D4; K=EMB2_; N=EMB2_; KP=KP2; kb=82; blk=bx-10896; }
    else                 { W=W5; D=D5; K=EMB2_; N=1280;  KP=KP2; kb=82; blk=bx-18112; }
    int k0 = (blk % kb) * 32, n0 = (blk / kb) * 32;
    int tx = threadIdx.x & 31, ty = threadIdx.x >> 5;
    #pragma unroll
    for (int j = 0; j < 4; ++j) {
        int k = k0 + ty + j * 8, n = n0 + tx;
        t[ty + j * 8][tx] = (k < K && n < N) ? W[(size_t)k * N + n] : 0.f;
    }
    __syncthreads();
    #pragma unroll
    for (int j = 0; j < 4; ++j) {
        int n = n0 + ty + j * 8, k = k0 + tx;
        D[(size_t)n * KP + k] = __float2half(t[tx][ty + j * 8]);
    }
}

// ---- stats1: stage-1 colstats (0..307) + kin colstats (308..327) + hist (328) ----
__global__ __launch_bounds__(256) void stats1_kernel(
    const float* __restrict__ X, const float* __restrict__ kin, const int* __restrict__ seq,
    float* __restrict__ psum, float* __restrict__ psq,
    float* __restrict__ psumK, float* __restrict__ psqK, int* __restrict__ cnt) {
    int bx = blockIdx.x;
    if (bx < 308) {
        int col = (bx % 7) * 256 + threadIdx.x;
        int chunk = bx / 7;
        float s = 0.f, q = 0.f;
        const float* p = X + (size_t)chunk * 256 * EMB_ + col;
        #pragma unroll 8
        for (int r = 0; r < 256; ++r, p += EMB_) { float v = *p; s += v; q += v * v; }
        psum[chunk * EMB_ + col] = s;
        psq [chunk * EMB_ + col] = q;
    } else if (bx < 328) {
        int b2 = bx - 308;
        int col = (b2 % 5) * 256 + threadIdx.x;
        int chunk = b2 / 5;
        float s = 0.f, q = 0.f;
        const float* p = kin + (size_t)chunk * 256 * D_SEQ_ + col;
        #pragma unroll 8
        for (int r = 0; r < 256; ++r, p += D_SEQ_) { float v = *p; s += v; q += v * v; }
        psumK[chunk * D_SEQ_ + col] = s;
        psqK [chunk * D_SEQ_ + col] = q;
    } else {
        __shared__ int h[21];
        if (threadIdx.x < 21) h[threadIdx.x] = 0;
        __syncthreads();
        for (int i = threadIdx.x; i < M_; i += blockDim.x) atomicAdd(&h[seq[i]], 1);
        __syncthreads();
        if (threadIdx.x < 21) cnt[threadIdx.x] = h[threadIdx.x];
    }
}

// ---- finalize_all1: stage-1 cols (idx<EMB_) + stage-2 kin/props cols ----
__global__ __launch_bounds__(256) void finalize_all1(
    const float* __restrict__ psum, const float* __restrict__ psq,
    const float* __restrict__ psumK, const float* __restrict__ psqK,
    const int* __restrict__ cnt,
    const float* __restrict__ g1g, const float* __restrict__ g1b,
    const float* __restrict__ r1g, const float* __restrict__ r1b,
    const float* __restrict__ g2g, const float* __restrict__ g2b,
    const float* __restrict__ r2g, const float* __restrict__ r2b,
    float* __restrict__ ss) {
    int idx = blockIdx.x * blockDim.x + threadIdx.x;
    if (idx < EMB_) {
        float s = 0.f, q = 0.f;
        for (int c = 0; c < NCHUNK_; ++c) { s += psum[c * EMB_ + idx]; q += psq[c * EMB_ + idx]; }
        float mean = s / (float)M_;
        float var  = q / (float)M_ - mean * mean;
        float inv  = rsqrtf(var + 1e-5f);
        float sa = g1g[idx] * inv;
        ss[0 * EMB2_ + idx] = sa; ss[1 * EMB2_ + idx] = g1b[idx] - mean * sa;
        float sb = r1g[idx] * inv;
        ss[2 * EMB2_ + idx] = sb; ss[3 * EMB2_ + idx] = r1b[idx] - mean * sb;
        return;
    }
    int col = D_SEQ_ + (idx - EMB_);   // [1280, 2564)
    if (col >= EMB2_) return;
    float mean, var;
    if (col < 2 * D_SEQ_) {
        int j = col - D_SEQ_;
        float s = 0.f, q = 0.f;
        for (int c = 0; c < 4; ++c) { s += psumK[c * D_SEQ_ + j]; q += psqK[c * D_SEQ_ + j]; }
        mean = s / (float)B_; var = q / (float)B_ - mean * mean;
    } else {
        int j = col - 2 * D_SEQ_;
        float s = 0.f;
        for (int sd = 0; sd < 21; ++sd) s += (float)cnt[sd] * c_props[sd * 4 + j];
        mean = s / (float)M_; var = mean - mean * mean;
    }
    float inv = rsqrtf(var + 1e-5f);
    float sa = g2g[col] * inv;
    ss[4 * EMB2_ + col] = sa; ss[5 * EMB2_ + col] = g2b[col] - mean * sa;
    float sb = r2g[col] * inv;
    ss[6 * EMB2_ + col] = sb; ss[7 * EMB2_ + col] = r2b[col] - mean * sb;
}

// ---- bn1: stage-1 XA/XB (y<M_) + kin KA/KB (y<M_+B_) + props tables (rest) ----
__global__ __launch_bounds__(256) void bn1_kernel(
    const float* __restrict__ X, const float* __restrict__ kin, const float* __restrict__ ss,
    const float* __restrict__ Wg2, const float* __restrict__ Wr21,
    float* __restrict__ Tg, float* __restrict__ Tr) {
    int row = blockIdx.y;
    int j = blockIdx.x * blockDim.x + threadIdx.x;
    if (row < M_) {
        if (j >= KP1 / 2) return;
        int c = j * 2;
        const float* xr = X + (size_t)row * EMB_;
        float v0 = xr[c], v1 = xr[c + 1];
        float a0 = fmaxf(fmaf(v0, ss[0 * EMB2_ + c], ss[1 * EMB2_ + c]), 0.f);
        float a1 = fmaxf(fmaf(v1, ss[0 * EMB2_ + c + 1], ss[1 * EMB2_ + c + 1]), 0.f);
        float b0 = fmaxf(fmaf(v0, ss[2 * EMB2_ + c], ss[3 * EMB2_ + c]), 0.f);
        float b1 = fmaxf(fmaf(v1, ss[2 * EMB2_ + c + 1], ss[3 * EMB2_ + c + 1]), 0.f);
        size_t o = (size_t)row * KP1 + c;
        *(__half2*)(g_XA + o) = __floats2half2_rn(a0, a1);
        *(__half2*)(g_XB + o) = __floats2half2_rn(b0, b1);
        return;
    }
    if (row < M_ + B_) {
        if (j >= D_SEQ_ / 2) return;
        int rb = row - M_;
        int c = j * 2;
        const float* xr = kin + (size_t)rb * D_SEQ_;
        const float* s1 = ss + 4 * EMB2_ + D_SEQ_;  const float* t1 = ss + 5 * EMB2_ + D_SEQ_;
        const float* s2 = ss + 6 * EMB2_ + D_SEQ_;  const float* t2 = ss + 7 * EMB2_ + D_SEQ_;
        float v0 = xr[c], v1 = xr[c + 1];
        float a0 = fmaxf(fmaf(v0, s1[c], t1[c]), 0.f);
        float a1 = fmaxf(fmaf(v1, s1[c + 1], t1[c + 1]), 0.f);
        float b0 = fmaxf(fmaf(v0, s2[c], t2[c]), 0.f);
        float b1 = fmaxf(fmaf(v1, s2[c + 1], t2[c + 1]), 0.f);
        size_t o = (size_t)rb * D_SEQ_ + c;
        *(__half2*)(g_KA + o) = __floats2half2_rn(a0, a1);
        *(__half2*)(g_KB + o) = __floats2half2_rn(b0, b1);
        return;
    }
    // props tables
    int p = row - M_ - B_;
    int idx = p * 1024 + j;
    if (idx >= NPROPS) return;
    const float* W; const float* s; const float* t; float* T; int N; int i;
    if (idx < 21 * D_SEQ_) {
        W = Wg2; s = ss + 4 * EMB2_ + 2 * D_SEQ_; t = ss + 5 * EMB2_ + 2 * D_SEQ_;
        T = Tg; N = D_SEQ_; i = idx;
    } else {
        i = idx - 21 * D_SEQ_;
        W = Wr21; s = ss + 6 * EMB2_ + 2 * D_SEQ_; t = ss + 7 * EMB2_ + 2 * D_SEQ_;
        T = Tr; N = EMB2_;
    }
    int sid = i / N, n = i % N;
    float acc = 0.f;
    #pragma unroll
    for (int jj = 0; jj < 4; ++jj) {
        float pv = fmaxf(fmaf(c_props[sid * 4 + jj], s[jj], t[jj]), 0.f);
        acc += pv * W[(size_t)(2 * D_SEQ_ + jj) * N + n];
    }
    T[i] = acc;
}

// ---- stats2: X2 colstats only ----
__global__ __launch_bounds__(256) void stats2_kernel(
    const float* __restrict__ X2, float* __restrict__ psum, float* __restrict__ psq) {
    int bx = blockIdx.x;
    int col = (bx % 5) * 256 + threadIdx.x;
    int chunk = bx / 5;
    float s = 0.f, q = 0.f;
    const float* p = X2 + (size_t)chunk * 256 * D_SEQ_ + col;
    #pragma unroll 8
    for (int r = 0; r < 256; ++r, p += D_SEQ_) { float v = *p; s += v; q += v * v; }
    psum[chunk * D_SEQ_ + col] = s;
    psq [chunk * D_SEQ_ + col] = q;
}

__global__ __launch_bounds__(256) void finalize2_kernel(
    const float* __restrict__ psum, const float* __restrict__ psq,
    const float* __restrict__ g2g, const float* __restrict__ g2b,
    const float* __restrict__ r2g, const float* __restrict__ r2b,
    float* __restrict__ ss) {
    int col = blockIdx.x * blockDim.x + threadIdx.x;
    if (col >= D_SEQ_) return;
    float s = 0.f, q = 0.f;
    for (int c = 0; c < NCHUNK_; ++c) { s += psum[c * D_SEQ_ + col]; q += psq[c * D_SEQ_ + col]; }
    float mean = s / (float)M_;
    float var  = q / (float)M_ - mean * mean;
    float inv  = rsqrtf(var + 1e-5f);
    float sa = g2g[col] * inv;
    ss[4 * EMB2_ + col] = sa; ss[5 * EMB2_ + col] = g2b[col] - mean * sa;
    float sb = r2g[col] * inv;
    ss[6 * EMB2_ + col] = sb; ss[7 * EMB2_ + col] = r2b[col] - mean * sb;
}

__global__ __launch_bounds__(256) void bn2x_kernel(
    const float* __restrict__ X2, const float* __restrict__ ss) {
    int j = blockIdx.x * blockDim.x + threadIdx.x;
    if (j >= D_SEQ_ / 2) return;
    int row = blockIdx.y;
    int c = j * 2;
    const float* xr = X2 + (size_t)row * D_SEQ_;
    float v0 = xr[c], v1 = xr[c + 1];
    float a0 = fmaxf(fmaf(v0, ss[4 * EMB2_ + c], ss[5 * EMB2_ + c]), 0.f);
    float a1 = fmaxf(fmaf(v1, ss[4 * EMB2_ + c + 1], ss[5 * EMB2_ + c + 1]), 0.f);
    float b0 = fmaxf(fmaf(v0, ss[6 * EMB2_ + c], ss[7 * EMB2_ + c]), 0.f);
    float b1 = fmaxf(fmaf(v1, ss[6 * EMB2_ + c + 1], ss[7 * EMB2_ + c + 1]), 0.f);
    size_t o = (size_t)row * D_SEQ_ + c;
    *(__half2*)(g_XA + o) = __floats2half2_rn(a0, a1);
    *(__half2*)(g_XB + o) = __floats2half2_rn(b0, b1);
}

// ---- GEMM parameter bundle ----
struct GemmArgs {
    const __half* A; const __half* Wt;
    const float* bias; float* Cf; __half* Ch;
    int lda, ldw, ktiles, Nout, Nzero, ldc;
    const float* Q; int ldq;
    const float* T; int ldt; const int* seq;
    const float* Pg; const float* NF; const float* avec;
    int gn;
};

__device__ __forceinline__ void gemm_body(const GemmArgs& P, int bxn, int bym) {
    extern __shared__ __half smh[];
    const unsigned sA_u = (unsigned)__cvta_generic_to_shared(smh);
    const unsigned sB_u = sA_u + (unsigned)(GSTAGES * GA_BUF) * 2u;

    const int tid  = threadIdx.x;
    const int bm   = bym * GBM;
    const int bn   = bxn * GBN;
    const int warp = tid >> 5, lane = tid & 31;
    const int wm = (warp & 1) << 6;
    const int wn = (warp >> 1) << 5;
    const int g  = lane >> 2, tg = lane & 3;

    const int t    = lane >> 3;
    const int a_m  = ((t & 1) << 3) + (lane & 7);
    const int a_ko = (t >> 1) << 3;
    const int b_n  = ((t >> 1) << 3) + (lane & 7);
    const int b_ko = (t & 1) << 3;

    float acc[4][4][4];
    #pragma unroll
    for (int mt = 0; mt < 4; ++mt)
        #pragma unroll
        for (int nt = 0; nt < 4; ++nt)
            #pragma unroll
            for (int i = 0; i < 4; ++i) acc[mt][nt][i] = 0.f;

    auto load_stage = [&](int kt, int buf) {
        const int k0 = kt * 64;
        unsigned sab = sA_u + (unsigned)(buf * GA_BUF) * 2u;
        #pragma unroll
        for (int it = 0; it < 4; ++it) {
            int idx = tid + it * 256;
            int row = idx >> 3, seg = idx & 7;
            cp16u(sab + (unsigned)(row * HS + seg * 8) * 2u,
                  P.A + (size_t)(bm + row) * P.lda + k0 + seg * 8);
        }
        unsigned sbb = sB_u + (unsigned)(buf * GB_BUF) * 2u;
        #pragma unroll
        for (int it = 0; it < 4; ++it) {
            int idx = tid + it * 256;
            int row = idx >> 3, seg = idx & 7;
            cp16u(sbb + (unsigned)(row * HS + seg * 8) * 2u,
                  P.Wt + (size_t)(bn + row) * P.ldw + k0 + seg * 8);
        }
        asm volatile("cp.async.commit_group;\n");
    };

    auto compute = [&](int buf) {
        const unsigned pA = sA_u + (unsigned)(buf * GA_BUF) * 2u;
        const unsigned pB = sB_u + (unsigned)(buf * GB_BUF) * 2u;
        #pragma unroll
        for (int kk = 0; kk < 4; ++kk) {
            unsigned af[4][4], bf[4][2];
            #pragma unroll
            for (int mt = 0; mt < 4; ++mt) {
                unsigned addr = pA + (unsigned)(((wm + (mt << 4) + a_m) * HS
                                                + (kk << 4) + a_ko) << 1);
                ldm4(af[mt][0], af[mt][1], af[mt][2], af[mt][3], addr);
            }
            #pragma unroll
            for (int p = 0; p < 2; ++p) {
                unsigned addr = pB + (unsigned)(((wn + (p << 4) + b_n) * HS
                                                + (kk << 4) + b_ko) << 1);
                ldm4(bf[2*p][0], bf[2*p][1], bf[2*p+1][0], bf[2*p+1][1], addr);
            }
            #pragma unroll
            for (int mt = 0; mt < 4; ++mt)
                #pragma unroll
                for (int nt = 0; nt < 4; ++nt)
                    mma_f16(acc[mt][nt], af[mt], bf[nt]);
        }
    };

    #pragma unroll
    for (int s = 0; s < GSTAGES - 1; ++s) load_stage(s, s);

    for (int kt = 0; kt < P.ktiles; ++kt) {
        asm volatile("cp.async.wait_group %0;\n" :: "n"(GSTAGES - 2));
        __syncthreads();
        int nxt = kt + GSTAGES - 1;
        if (nxt < P.ktiles) load_stage(nxt, nxt % GSTAGES);
        else asm volatile("cp.async.commit_group;\n");
        compute(kt % GSTAGES);
    }

    float ca0 = 0.f, ca1 = 0.f;
    if (P.avec) { ca0 = P.avec[0]; ca1 = P.avec[1]; }

    #pragma unroll
    for (int mt = 0; mt < 4; ++mt) {
        int r = bm + wm + (mt << 4);
        int m0 = r + g, m1 = r + g + 8;
        const float* q0 = P.Q ? P.Q + (size_t)(m0 / 11) * P.ldq : nullptr;
        const float* q1 = P.Q ? P.Q + (size_t)(m1 / 11) * P.ldq : nullptr;
        const float* t0 = P.T ? P.T + (size_t)P.seq[m0] * P.ldt : nullptr;
        const float* t1p = P.T ? P.T + (size_t)P.seq[m1] * P.ldt : nullptr;
        #pragma unroll
        for (int nt = 0; nt < 4; ++nt) {
            int c = bn + wn + (nt << 3) + (tg << 1);
            #pragma unroll
            for (int half = 0; half < 2; ++half) {
                int cc = c + half;
                if (cc >= P.Nzero) continue;
                float v0 = 0.f, v1 = 0.f;
                if (cc < P.Nout) {
                    float bb = P.bias ? P.bias[cc] : 0.f;
                    v0 = acc[mt][nt][half]     + bb;
                    v1 = acc[mt][nt][half + 2] + bb;
                    if (q0) { v0 += q0[cc]; v1 += q1[cc]; }
                    if (t0) { v0 += t0[cc]; v1 += t1p[cc]; }
                }
                if (P.avec) {
                    float p0 = P.Pg[(size_t)m0 * P.ldc + cc], n0v = P.NF[(size_t)m0 * P.ldc + cc];
                    float p1 = P.Pg[(size_t)m1 * P.ldc + cc], n1v = P.NF[(size_t)m1 * P.ldc + cc];
                    P.Cf[(size_t)m0 * P.ldc + cc] = sigmoidf_(p0) * n0v * ca0 + v0 * ca1;
                    P.Cf[(size_t)m1 * P.ldc + cc] = sigmoidf_(p1) * n1v * ca0 + v1 * ca1;
                } else if (P.Ch) {
                    P.Ch[(size_t)m0 * P.ldc + cc] = __float2half(fmaxf(v0, 0.f));
                    P.Ch[(size_t)m1 * P.ldc + cc] = __float2half(fmaxf(v1, 0.f));
                } else if (cc < P.Nout) {
                    P.Cf[(size_t)m0 * P.ldc + cc] = v0;
                    P.Cf[(size_t)m1 * P.ldc + cc] = v1;
                }
            }
        }
    }
}

__global__ __launch_bounds__(256, 2) void gemm_single(GemmArgs P) {
    gemm_body(P, blockIdx.x, blockIdx.y);
}
__global__ __launch_bounds__(256, 2) void gemm_dual(GemmArgs Pa, GemmArgs Pb, int na) {
    int i = blockIdx.x;
    if (i < na) gemm_body(Pa, i % Pa.gn, i / Pa.gn);
    else { i -= na; gemm_body(Pb, i % Pb.gn, i / Pb.gn); }
}
__global__ __launch_bounds__(256, 2) void gemm_quad(
    GemmArgs Pa, GemmArgs Pb, GemmArgs Pc, GemmArgs Pd, int na, int nb, int nc) {
    int i = blockIdx.x;
    if (i < na) { gemm_body(Pa, i % Pa.gn, i / Pa.gn); return; }
    i -= na;
    if (i < nb) { gemm_body(Pb, i % Pb.gn, i / Pb.gn); return; }
    i -= nb;
    if (i < nc) { gemm_body(Pc, i % Pc.gn, i / Pc.gn); return; }
    i -= nc;
    gemm_body(Pd, i % Pd.gn, i / Pd.gn);
}

__global__ __launch_bounds__(256) void final_kernel(
    const float* __restrict__ G1, const float* __restrict__ G2,
    const float* __restrict__ X2, const float* __restrict__ a2,
    float* __restrict__ out) {
    int b = blockIdx.x;
    float s0 = a2[0], s1 = a2[1];
    for (int i = threadIdx.x; i < D_SEQ_ / 4; i += blockDim.x) {
        float4 acc = make_float4(0.f, 0.f, 0.f, 0.f);
        for (int k = 0; k < K_; ++k) {
            size_t m = (size_t)b * K_ + k;
            float4 f1 = *(const float4*)(G1 + m * D_SEQ_ + i * 4);
            float4 f2 = *(const float4*)(G2 + m * D_SEQ_ + i * 4);
            float4 gn = *(const float4*)(X2 + m * D_SEQ_ + i * 4);
            acc.x += sigmoidf_(f1.x) * gn.x * s0 + f2.x * s1;
            acc.y += sigmoidf_(f1.y) * gn.y * s0 + f2.y * s1;
            acc.z += sigmoidf_(f1.z) * gn.z * s0 + f2.z * s1;
            acc.w += sigmoidf_(f1.w) * gn.w * s0 + f2.w * s1;
        }
        *(float4*)(out + (size_t)b * D_SEQ_ + i * 4) = acc;
    }
}

static GemmArgs mk(const __half* A, const __half* Wt, const float* bias,
                   float* Cf, __half* Ch, int lda, int ldw, int ktiles,
                   int Nout, int Nzero, int ldc,
                   const float* Q, int ldq, const float* T, int ldt, const int* seq,
                   const float* Pg, const float* NF, const float* avec, int gn) {
    GemmArgs p;
    p.A = A; p.Wt = Wt; p.bias = bias; p.Cf = Cf; p.Ch = Ch;
    p.lda = lda; p.ldw = ldw; p.ktiles = ktiles;
    p.Nout = Nout; p.Nzero = Nzero; p.ldc = ldc;
    p.Q = Q; p.ldq = ldq; p.T = T; p.ldt = ldt; p.seq = seq;
    p.Pg = Pg; p.NF = NF; p.avec = avec; p.gn = gn;
    return p;
}

extern "C" void kernel_launch(void* const* d_in, const int* in_sizes, int n_in,
                              void* d_out, int out_size) {
    const float* kin_in   = (const float*)d_in[0];
    const float* sub      = (const float*)d_in[1];
    const float* n2       = (const float*)d_in[2];
    const float* a        = (const float*)d_in[4];
    const float* a2       = (const float*)d_in[5];
    const float* phos     = (const float*)d_in[6];
    const float* g1_gamma = (const float*)d_in[7];
    const float* g1_beta  = (const float*)d_in[8];
    const float* g1_W     = (const float*)d_in[9];
    const float* g1_b     = (const float*)d_in[10];
    const float* r1_gamma = (const float*)d_in[11];
    const float* r1_beta  = (const float*)d_in[12];
    const float* r1_W1    = (const float*)d_in[13];
    const float* r1_b1    = (const float*)d_in[14];
    const float* r1_W2    = (const float*)d_in[15];
    const float* r1_b2    = (const float*)d_in[16];
    const float* g2_gamma = (const float*)d_in[17];
    const float* g2_beta  = (const float*)d_in[18];
    const float* g2_W     = (const float*)d_in[19];
    const float* g2_b     = (const float*)d_in[20];
    const float* r2_gamma = (const float*)d_in[21];
    const float* r2_beta  = (const float*)d_in[22];
    const float* r2_W1    = (const float*)d_in[23];
    const float* r2_b1    = (const float*)d_in[24];
    const float* r2_W2    = (const float*)d_in[25];
    const float* r2_b2    = (const float*)d_in[26];
    const int*   position = (const int*)d_in[27];
    const int*   raw_seq  = (const int*)d_in[28];

    float* out = (float*)d_out;
    float* graph_feature = out;
    float* node_feature  = out + (size_t)B_ * D_SEQ_;

    float *X, *P1, *P2, *kin, *Qg, *Qr, *Tg, *Tr, *psum, *psq, *psumK, *psqK, *ss;
    int* cnt;
    __half *Y, *XA, *XB, *KA, *KB, *Wt;
    cudaGetSymbolAddress((void**)&X,     g_X);
    cudaGetSymbolAddress((void**)&Y,     g_Y);
    cudaGetSymbolAddress((void**)&XA,    g_XA);
    cudaGetSymbolAddress((void**)&XB,    g_XB);
    cudaGetSymbolAddress((void**)&KA,    g_KA);
    cudaGetSymbolAddress((void**)&KB,    g_KB);
    cudaGetSymbolAddress((void**)&P1,    g_P1);
    cudaGetSymbolAddress((void**)&P2,    g_P2);
    cudaGetSymbolAddress((void**)&Wt,    g_Wt);
    cudaGetSymbolAddress((void**)&kin,   g_kin);
    cudaGetSymbolAddress((void**)&Qg,    g_Qg);
    cudaGetSymbolAddress((void**)&Qr,    g_Qr);
    cudaGetSymbolAddress((void**)&Tg,    g_Tg);
    cudaGetSymbolAddress((void**)&Tr,    g_Tr);
    cudaGetSymbolAddress((void**)&cnt,   g_cnt);
    cudaGetSymbolAddress((void**)&psum,  g_psum);
    cudaGetSymbolAddress((void**)&psq,   g_psq);
    cudaGetSymbolAddress((void**)&psumK, g_psumK);
    cudaGetSymbolAddress((void**)&psqK,  g_psqK);
    cudaGetSymbolAddress((void**)&ss,    g_ss);

    cudaFuncSetAttribute(gemm_single, cudaFuncAttributeMaxDynamicSharedMemorySize, GSMEM_BYTES);
    cudaFuncSetAttribute(gemm_dual,   cudaFuncAttributeMaxDynamicSharedMemorySize, GSMEM_BYTES);
    cudaFuncSetAttribute(gemm_quad,   cudaFuncAttributeMaxDynamicSharedMemorySize, GSMEM_BYTES);

    __half* Wt_g1  = Wt;
    __half* Wt_r11 = Wt_g1  + (size_t)1280 * KP1;
    __half* Wt_r12 = Wt_r11 + (size_t)1792 * KP1;
    __half* Wt_g2  = Wt_r12 + (size_t)1280 * KP1;
    __half* Wt_r21 = Wt_g2  + (size_t)1280 * KP2;
    __half* Wt_r22 = Wt_r21 + (size_t)NP_R21 * KP2;

    // 1. prep
    prep_kernel<<<NB_BUILD + 21392, 256>>>(
        g1_W, r1_W1, r1_W2, g2_W, r2_W1, r2_W2,
        Wt_g1, Wt_r11, Wt_r12, Wt_g2, Wt_r21, Wt_r22,
        kin_in, sub, n2, phos, position, kin, X, node_feature);

    // 2. merged stats (stage-1 + kin + hist)
    stats1_kernel<<<329, 256>>>(X, kin, raw_seq, psum, psq, psumK, psqK, cnt);

    // 3. merged finalize (stage-1 cols + stage-2 kin/props cols)
    finalize_all1<<<(EMB_ + 1284 + 255) / 256, 256>>>(psum, psq, psumK, psqK, cnt,
        g1_gamma, g1_beta, r1_gamma, r1_beta, g2_gamma, g2_beta, r2_gamma, r2_beta, ss);

    // 4. merged transform (XA/XB + KA/KB + props tables)
    bn1_kernel<<<dim3(4, M_ + B_ + (NPROPS + 1023) / 1024), 256>>>(
        X, kin, ss, g2_W, r2_W1, Tg, Tr);

    // 5. quad GEMM: r11 + g1 + Qr + Qg (2360 CTAs)
    {
        GemmArgs pr11 = mk(XB, Wt_r11, r1_b1, nullptr, Y, KP1, KP1, 28, 1792, 1792, KP1,
                           nullptr, 0, nullptr, 0, nullptr, nullptr, nullptr, nullptr, 14);
        GemmArgs pg1  = mk(XA, Wt_g1,  g1_b,  P1, nullptr, KP1, KP1, 28, 1280, 1280, 1280,
                           nullptr, 0, nullptr, 0, nullptr, nullptr, nullptr, nullptr, 10);
        GemmArgs pqr  = mk(KB, Wt_r21 + 1280, nullptr, Qr, nullptr, D_SEQ_, KP2, 20,
                           EMB2_, EMB2_, EMB2_, nullptr, 0, nullptr, 0, nullptr,
                           nullptr, nullptr, nullptr, 21);
        GemmArgs pqg  = mk(KA, Wt_g2 + 1280, nullptr, Qg, nullptr, D_SEQ_, KP2, 20,
                           1280, 1280, 1280, nullptr, 0, nullptr, 0, nullptr,
                           nullptr, nullptr, nullptr, 10);
        gemm_quad<<<1232 + 880 + 168 + 80, 256, GSMEM_BYTES>>>(
            pr11, pg1, pqr, pqg, 1232, 880, 168);
    }

    // 6. r12 with fused combine -> X2
    {
        GemmArgs pr12 = mk(Y, Wt_r12, r1_b2, X, nullptr, KP1, KP1, 28, 1280, 1280, 1280,
                           nullptr, 0, nullptr, 0, nullptr, P1, node_feature, a, 10);
        gemm_single<<<dim3(10, 88), 256, GSMEM_BYTES>>>(pr12);
    }

    // 7-9. X2 stats -> finalize -> transform
    stats2_kernel<<<220, 256>>>(X, psum, psq);
    finalize2_kernel<<<5, 256>>>(psum, psq, g2_gamma, g2_beta, r2_gamma, r2_beta, ss);
    bn2x_kernel<<<dim3(3, M_), 256>>>(X, ss);

    // 10. stage-2 main dual: r21 + g2 (Q/T in epilogue)
    {
        GemmArgs pr21 = mk(XB, Wt_r21, r2_b1, nullptr, Y, D_SEQ_, KP2, 20, EMB2_, KP2, KP2,
                           Qr, EMB2_, Tr, EMB2_, raw_seq, nullptr, nullptr, nullptr, 21);
        GemmArgs pg2  = mk(XA, Wt_g2,  g2_b,  P1, nullptr, D_SEQ_, KP2, 20, 1280, 1280, 1280,
                           Qg, 1280, Tg, 1280, raw_seq, nullptr, nullptr, nullptr, 10);
        gemm_dual<<<21 * 88 + 10 * 88, 256, GSMEM_BYTES>>>(pr21, pg2, 21 * 88);
    }

    // 11. r22
    {
        GemmArgs pr22 = mk(Y, Wt_r22, r2_b2, P2, nullptr, KP2, KP2, 41, 1280, 1280, 1280,
                           nullptr, 0, nullptr, 0, nullptr, nullptr, nullptr, nullptr, 10);
        gemm_single<<<dim3(10, 88), 256, GSMEM_BYTES>>>(pr22);
    }

    // 12. final combine + K-reduce
    final_kernel<<<B_, 256>>>(P1, P2, X, a2, graph_feature);
}

// round 16
// speedup vs baseline: 1.1727x; 1.0084x over previous
#include <cuda_runtime.h>
#include <cuda_fp16.h>
#include <cstdint>

#define B_      1024
#define K_      11
#define L_KIN_  128
#define L_SUB_  64
#define L_STR_  128
#define D_SEQ_  1280
#define D_STR_  512
#define EMB_    1792
#define EMB2_   2564
#define M_      (B_ * K_)
#define NCHUNK_ 44
#define KP1     1792
#define KP2     2624
#define NP_R21  2816
#define NB_BUILD (B_ * (K_ + 1))
#define NPROPS  (21 * (D_SEQ_ + EMB2_))

#define GBM 128
#define GBN 128
#define GSTAGES 3
#define HS 72
#define GA_BUF (GBM * HS)
#define GB_BUF (GBN * HS)
#define GSMEM_BYTES (GSTAGES * (GA_BUF + GB_BUF) * 2)   // 110592

__device__ float  g_X [(size_t)M_ * EMB_];
__device__ __half g_Y [(size_t)M_ * KP2];
__device__ __half g_XA[(size_t)M_ * KP1];
__device__ __half g_XB[(size_t)M_ * KP1];
__device__ __half g_KA[(size_t)B_ * D_SEQ_];
__device__ __half g_KB[(size_t)B_ * D_SEQ_];
__device__ float  g_P1[(size_t)M_ * D_SEQ_];
__device__ float  g_P2[(size_t)M_ * D_SEQ_];
__device__ __half g_Wt[21905408];
__device__ float  g_kin[(size_t)B_ * D_SEQ_];
__device__ float  g_Qg[(size_t)B_ * D_SEQ_];
__device__ float  g_Qr[(size_t)B_ * EMB2_];
__device__ float  g_Tg[21 * D_SEQ_];
__device__ float  g_Tr[21 * EMB2_];
__device__ int    g_cnt[21];
__device__ float  g_psum [NCHUNK_ * EMB_];
__device__ float  g_psq  [NCHUNK_ * EMB_];
__device__ float  g_psumK[4 * D_SEQ_];
__device__ float  g_psqK [4 * D_SEQ_];
__device__ float  g_ss  [8 * EMB2_];

__constant__ float c_props[21 * 4] = {
    0,0,0,0,  1,0,0,0,  0,0,0,0,  0,0,0,0,  1,0,0,0,  0,0,0,0,  0,0,0,0,
    1,0,0,0,  1,0,0,0,  0,0,0,0,  0,0,1,0,  0,0,0,0,  0,0,0,1,  0,0,1,0,
    1,0,0,0,  0,0,0,1,  0,1,0,0,  0,0,0,1,  0,1,0,0,  0,1,0,0,  0,0,0,0
};

__device__ __forceinline__ float sigmoidf_(float x) { return 1.f / (1.f + expf(-x)); }

__device__ __forceinline__ void mma_f16(float* d, const unsigned* a, const unsigned* b) {
    asm volatile(
        "mma.sync.aligned.m16n8k16.row.col.f32.f16.f16.f32 "
        "{%0,%1,%2,%3}, {%4,%5,%6,%7}, {%8,%9}, {%0,%1,%2,%3};\n"
        : "+f"(d[0]), "+f"(d[1]), "+f"(d[2]), "+f"(d[3])
        : "r"(a[0]), "r"(a[1]), "r"(a[2]), "r"(a[3]), "r"(b[0]), "r"(b[1]));
}
__device__ __forceinline__ void cp16u(unsigned dst, const void* src) {
    asm volatile("cp.async.cg.shared.global [%0], [%1], 16;\n" :: "r"(dst), "l"(src));
}
__device__ __forceinline__ void ldm4(unsigned& r0, unsigned& r1, unsigned& r2, unsigned& r3,
                                     unsigned addr) {
    asm volatile("ldmatrix.sync.aligned.m8n8.x4.shared.b16 {%0,%1,%2,%3}, [%4];"
                 : "=r"(r0), "=r"(r1), "=r"(r2), "=r"(r3) : "r"(addr));
}

// ---- prep: heavy build/kin blocks FIRST, weight transpose after ----
// X gets ONLY gf2 columns [1280,1792); gf1 columns live in node_feature (+phos on mid rows, applied by consumers).
__global__ __launch_bounds__(256) void prep_kernel(
    const float* __restrict__ W0, const float* __restrict__ W1, const float* __restrict__ W2,
    const float* __restrict__ W3, const float* __restrict__ W4, const float* __restrict__ W5,
    __half* __restrict__ D0, __half* __restrict__ D1, __half* __restrict__ D2,
    __half* __restrict__ D3, __half* __restrict__ D4, __half* __restrict__ D5,
    const float* __restrict__ kin_in, const float* __restrict__ sub,
    const float* __restrict__ n2, const float* __restrict__ phos,
    const int* __restrict__ position,
    float* __restrict__ kin_out, float* __restrict__ X, float* __restrict__ node_feature) {
    __shared__ float t[32][33];
    int bx = blockIdx.x;
    if (bx < NB_BUILD) {
        int b = bx / (K_ + 1), k = bx % (K_ + 1);
        if (k == K_) {
            const float* base = kin_in + ((size_t)b * L_KIN_ + 1) * D_SEQ_;
            for (int i = threadIdx.x; i < D_SEQ_ / 4; i += blockDim.x) {
                float4 acc = make_float4(0.f, 0.f, 0.f, 0.f);
                #pragma unroll 8
                for (int r = 0; r < L_KIN_ - 1; ++r) {
                    float4 v = *(const float4*)(base + (size_t)r * D_SEQ_ + i * 4);
                    acc.x += v.x; acc.y += v.y; acc.z += v.z; acc.w += v.w;
                }
                const float inv = 1.f / 127.f;
                *(float4*)(kin_out + (size_t)b * D_SEQ_ + i * 4) =
                    make_float4(acc.x * inv, acc.y * inv, acc.z * inv, acc.w * inv);
            }
            return;
        }
        size_t m = (size_t)b * K_ + k;
        const float* src1 = sub + ((size_t)b * L_SUB_ + 1 + k) * D_SEQ_;
        float* dst = X + m * EMB_;
        float* nf  = node_feature + m * D_SEQ_;
        bool mid = (k == K_ / 2);
        for (int i = threadIdx.x; i < D_SEQ_ / 4; i += blockDim.x)
            *(float4*)(nf + i * 4) = *(const float4*)(src1 + i * 4);
        int row = position[b] + k - K_ / 2;
        bool ok = (row >= 0 && row < L_STR_);
        const float* src2 = n2 + ((size_t)b * L_STR_ + (ok ? row : 0)) * D_STR_;
        for (int i = threadIdx.x; i < D_STR_ / 4; i += blockDim.x) {
            float4 v = make_float4(0.f, 0.f, 0.f, 0.f);
            if (ok) v = *(const float4*)(src2 + i * 4);
            if (mid) {
                float4 p = *(const float4*)(phos + D_SEQ_ + i * 4);
                v.x += p.x; v.y += p.y; v.z += p.z; v.w += p.w;
            }
            *(float4*)(dst + D_SEQ_ + i * 4) = v;
        }
        return;
    }
    bx -= NB_BUILD;
    const float* W; __half* D; int K, N, KP, kb, blk;
    if      (bx < 2240)  { W=W0; D=D0; K=EMB_;  N=1280;  KP=KP1; kb=56; blk=bx; }
    else if (bx < 5376)  { W=W1; D=D1; K=EMB_;  N=1792;  KP=KP1; kb=56; blk=bx-2240; }
    else if (bx < 7616)  { W=W2; D=D2; K=EMB_;  N=1280;  KP=KP1; kb=56; blk=bx-5376; }
    else if (bx < 10896) { W=W3; D=D3; K=EMB2_; N=1280;  KP=KP2; kb=82; blk=bx-7616; }
    else if (bx < 18112) { W=W4; D=D4; K=EMB2_; N=EMB2_; KP=KP2; kb=82; blk=bx-10896; }
    else                 { W=W5; D=D5; K=EMB2_; N=1280;  KP=KP2; kb=82; blk=bx-18112; }
    int k0 = (blk % kb) * 32, n0 = (blk / kb) * 32;
    int tx = threadIdx.x & 31, ty = threadIdx.x >> 5;
    #pragma unroll
    for (int j = 0; j < 4; ++j) {
        int k = k0 + ty + j * 8, n = n0 + tx;
        t[ty + j * 8][tx] = (k < K && n < N) ? W[(size_t)k * N + n] : 0.f;
    }
    __syncthreads();
    #pragma unroll
    for (int j = 0; j < 4; ++j) {
        int n = n0 + ty + j * 8, k = k0 + tx;
        D[(size_t)n * KP + k] = __float2half(t[tx][ty + j * 8]);
    }
}

// ---- stats1: stage-1 colstats (gf1 from nf + phos-on-mid; gf2 from X) + kin + hist ----
__global__ __launch_bounds__(256) void stats1_kernel(
    const float* __restrict__ X, const float* __restrict__ nf, const float* __restrict__ phos,
    const float* __restrict__ kin, const int* __restrict__ seq,
    float* __restrict__ psum, float* __restrict__ psq,
    float* __restrict__ psumK, float* __restrict__ psqK, int* __restrict__ cnt) {
    int bx = blockIdx.x;
    if (bx < 308) {
        int col = (bx % 7) * 256 + threadIdx.x;
        int chunk = bx / 7;
        int r0 = chunk * 256;
        float s = 0.f, q = 0.f;
        if (col < D_SEQ_) {
            float ph = phos[col];
            const float* p = nf + (size_t)r0 * D_SEQ_ + col;
            int kk = r0 % K_;
            for (int r = 0; r < 256; ++r, p += D_SEQ_) {
                float v = *p;
                if (kk == K_ / 2) v += ph;
                if (++kk == K_) kk = 0;
                s += v; q += v * v;
            }
        } else {
            const float* p = X + (size_t)r0 * EMB_ + col;
            #pragma unroll 8
            for (int r = 0; r < 256; ++r, p += EMB_) { float v = *p; s += v; q += v * v; }
        }
        psum[chunk * EMB_ + col] = s;
        psq [chunk * EMB_ + col] = q;
    } else if (bx < 328) {
        int b2 = bx - 308;
        int col = (b2 % 5) * 256 + threadIdx.x;
        int chunk = b2 / 5;
        float s = 0.f, q = 0.f;
        const float* p = kin + (size_t)chunk * 256 * D_SEQ_ + col;
        #pragma unroll 8
        for (int r = 0; r < 256; ++r, p += D_SEQ_) { float v = *p; s += v; q += v * v; }
        psumK[chunk * D_SEQ_ + col] = s;
        psqK [chunk * D_SEQ_ + col] = q;
    } else {
        __shared__ int h[21];
        if (threadIdx.x < 21) h[threadIdx.x] = 0;
        __syncthreads();
        for (int i = threadIdx.x; i < M_; i += blockDim.x) atomicAdd(&h[seq[i]], 1);
        __syncthreads();
        if (threadIdx.x < 21) cnt[threadIdx.x] = h[threadIdx.x];
    }
}

__global__ __launch_bounds__(256) void finalize_all1(
    const float* __restrict__ psum, const float* __restrict__ psq,
    const float* __restrict__ psumK, const float* __restrict__ psqK,
    const int* __restrict__ cnt,
    const float* __restrict__ g1g, const float* __restrict__ g1b,
    const float* __restrict__ r1g, const float* __restrict__ r1b,
    const float* __restrict__ g2g, const float* __restrict__ g2b,
    const float* __restrict__ r2g, const float* __restrict__ r2b,
    float* __restrict__ ss) {
    int idx = blockIdx.x * blockDim.x + threadIdx.x;
    if (idx < EMB_) {
        float s = 0.f, q = 0.f;
        for (int c = 0; c < NCHUNK_; ++c) { s += psum[c * EMB_ + idx]; q += psq[c * EMB_ + idx]; }
        float mean = s / (float)M_;
        float var  = q / (float)M_ - mean * mean;
        float inv  = rsqrtf(var + 1e-5f);
        float sa = g1g[idx] * inv;
        ss[0 * EMB2_ + idx] = sa; ss[1 * EMB2_ + idx] = g1b[idx] - mean * sa;
        float sb = r1g[idx] * inv;
        ss[2 * EMB2_ + idx] = sb; ss[3 * EMB2_ + idx] = r1b[idx] - mean * sb;
        return;
    }
    int col = D_SEQ_ + (idx - EMB_);
    if (col >= EMB2_) return;
    float mean, var;
    if (col < 2 * D_SEQ_) {
        int j = col - D_SEQ_;
        float s = 0.f, q = 0.f;
        for (int c = 0; c < 4; ++c) { s += psumK[c * D_SEQ_ + j]; q += psqK[c * D_SEQ_ + j]; }
        mean = s / (float)B_; var = q / (float)B_ - mean * mean;
    } else {
        int j = col - 2 * D_SEQ_;
        float s = 0.f;
        for (int sd = 0; sd < 21; ++sd) s += (float)cnt[sd] * c_props[sd * 4 + j];
        mean = s / (float)M_; var = mean - mean * mean;
    }
    float inv = rsqrtf(var + 1e-5f);
    float sa = g2g[col] * inv;
    ss[4 * EMB2_ + col] = sa; ss[5 * EMB2_ + col] = g2b[col] - mean * sa;
    float sb = r2g[col] * inv;
    ss[6 * EMB2_ + col] = sb; ss[7 * EMB2_ + col] = r2b[col] - mean * sb;
}

// ---- bn1: stage-1 XA/XB (gf1 from nf + phos-on-mid, gf2 from X) + kin KA/KB + props ----
__global__ __launch_bounds__(256) void bn1_kernel(
    const float* __restrict__ X, const float* __restrict__ nf, const float* __restrict__ phos,
    const float* __restrict__ kin, const float* __restrict__ ss,
    const float* __restrict__ Wg2, const float* __restrict__ Wr21,
    float* __restrict__ Tg, float* __restrict__ Tr) {
    int row = blockIdx.y;
    int j = blockIdx.x * blockDim.x + threadIdx.x;
    if (row < M_) {
        if (j >= KP1 / 2) return;
        int c = j * 2;
        float v0, v1;
        if (c < D_SEQ_) {
            const float* xr = nf + (size_t)row * D_SEQ_;
            v0 = xr[c]; v1 = xr[c + 1];
            if (row % K_ == K_ / 2) { v0 += phos[c]; v1 += phos[c + 1]; }
        } else {
            const float* xr = X + (size_t)row * EMB_;
            v0 = xr[c]; v1 = xr[c + 1];
        }
        float a0 = fmaxf(fmaf(v0, ss[0 * EMB2_ + c], ss[1 * EMB2_ + c]), 0.f);
        float a1 = fmaxf(fmaf(v1, ss[0 * EMB2_ + c + 1], ss[1 * EMB2_ + c + 1]), 0.f);
        float b0 = fmaxf(fmaf(v0, ss[2 * EMB2_ + c], ss[3 * EMB2_ + c]), 0.f);
        float b1 = fmaxf(fmaf(v1, ss[2 * EMB2_ + c + 1], ss[3 * EMB2_ + c + 1]), 0.f);
        size_t o = (size_t)row * KP1 + c;
        *(__half2*)(g_XA + o) = __floats2half2_rn(a0, a1);
        *(__half2*)(g_XB + o) = __floats2half2_rn(b0, b1);
        return;
    }
    if (row < M_ + B_) {
        if (j >= D_SEQ_ / 2) return;
        int rb = row - M_;
        int c = j * 2;
        const float* xr = kin + (size_t)rb * D_SEQ_;
        const float* s1 = ss + 4 * EMB2_ + D_SEQ_;  const float* t1 = ss + 5 * EMB2_ + D_SEQ_;
        const float* s2 = ss + 6 * EMB2_ + D_SEQ_;  const float* t2 = ss + 7 * EMB2_ + D_SEQ_;
        float v0 = xr[c], v1 = xr[c + 1];
        float a0 = fmaxf(fmaf(v0, s1[c], t1[c]), 0.f);
        float a1 = fmaxf(fmaf(v1, s1[c + 1], t1[c + 1]), 0.f);
        float b0 = fmaxf(fmaf(v0, s2[c], t2[c]), 0.f);
        float b1 = fmaxf(fmaf(v1, s2[c + 1], t2[c + 1]), 0.f);
        size_t o = (size_t)rb * D_SEQ_ + c;
        *(__half2*)(g_KA + o) = __floats2half2_rn(a0, a1);
        *(__half2*)(g_KB + o) = __floats2half2_rn(b0, b1);
        return;
    }
    int p = row - M_ - B_;
    int idx = p * 1024 + j;
    if (idx >= NPROPS) return;
    const float* W; const float* s; const float* t; float* T; int N; int i;
    if (idx < 21 * D_SEQ_) {
        W = Wg2; s = ss + 4 * EMB2_ + 2 * D_SEQ_; t = ss + 5 * EMB2_ + 2 * D_SEQ_;
        T = Tg; N = D_SEQ_; i = idx;
    } else {
        i = idx - 21 * D_SEQ_;
        W = Wr21; s = ss + 6 * EMB2_ + 2 * D_SEQ_; t = ss + 7 * EMB2_ + 2 * D_SEQ_;
        T = Tr; N = EMB2_;
    }
    int sid = i / N, n = i % N;
    float acc = 0.f;
    #pragma unroll
    for (int jj = 0; jj < 4; ++jj) {
        float pv = fmaxf(fmaf(c_props[sid * 4 + jj], s[jj], t[jj]), 0.f);
        acc += pv * W[(size_t)(2 * D_SEQ_ + jj) * N + n];
    }
    T[i] = acc;
}

__global__ __launch_bounds__(256) void stats2_kernel(
    const float* __restrict__ X2, float* __restrict__ psum, float* __restrict__ psq) {
    int bx = blockIdx.x;
    int col = (bx % 5) * 256 + threadIdx.x;
    int chunk = bx / 5;
    float s = 0.f, q = 0.f;
    const float* p = X2 + (size_t)chunk * 256 * D_SEQ_ + col;
    #pragma unroll 8
    for (int r = 0; r < 256; ++r, p += D_SEQ_) { float v = *p; s += v; q += v * v; }
    psum[chunk * D_SEQ_ + col] = s;
    psq [chunk * D_SEQ_ + col] = q;
}

__global__ __launch_bounds__(256) void finalize2_kernel(
    const float* __restrict__ psum, const float* __restrict__ psq,
    const float* __restrict__ g2g, const float* __restrict__ g2b,
    const float* __restrict__ r2g, const float* __restrict__ r2b,
    float* __restrict__ ss) {
    int col = blockIdx.x * blockDim.x + threadIdx.x;
    if (col >= D_SEQ_) return;
    float s = 0.f, q = 0.f;
    for (int c = 0; c < NCHUNK_; ++c) { s += psum[c * D_SEQ_ + col]; q += psq[c * D_SEQ_ + col]; }
    float mean = s / (float)M_;
    float var  = q / (float)M_ - mean * mean;
    float inv  = rsqrtf(var + 1e-5f);
    float sa = g2g[col] * inv;
    ss[4 * EMB2_ + col] = sa; ss[5 * EMB2_ + col] = g2b[col] - mean * sa;
    float sb = r2g[col] * inv;
    ss[6 * EMB2_ + col] = sb; ss[7 * EMB2_ + col] = r2b[col] - mean * sb;
}

__global__ __launch_bounds__(256) void bn2x_kernel(
    const float* __restrict__ X2, const float* __restrict__ ss) {
    int j = blockIdx.x * blockDim.x + threadIdx.x;
    if (j >= D_SEQ_ / 2) return;
    int row = blockIdx.y;
    int c = j * 2;
    const float* xr = X2 + (size_t)row * D_SEQ_;
    float v0 = xr[c], v1 = xr[c + 1];
    float a0 = fmaxf(fmaf(v0, ss[4 * EMB2_ + c], ss[5 * EMB2_ + c]), 0.f);
    float a1 = fmaxf(fmaf(v1, ss[4 * EMB2_ + c + 1], ss[5 * EMB2_ + c + 1]), 0.f);
    float b0 = fmaxf(fmaf(v0, ss[6 * EMB2_ + c], ss[7 * EMB2_ + c]), 0.f);
    float b1 = fmaxf(fmaf(v1, ss[6 * EMB2_ + c + 1], ss[7 * EMB2_ + c + 1]), 0.f);
    size_t o = (size_t)row * D_SEQ_ + c;
    *(__half2*)(g_XA + o) = __floats2half2_rn(a0, a1);
    *(__half2*)(g_XB + o) = __floats2half2_rn(b0, b1);
}

struct GemmArgs {
    const __half* A; const __half* Wt;
    const float* bias; float* Cf; __half* Ch;
    int lda, ldw, ktiles, Nout, Nzero, ldc;
    const float* Q; int ldq;
    const float* T; int ldt; const int* seq;
    const float* Pg; const float* NF; const float* avec;
    int gn;
};

__device__ __forceinline__ void gemm_body(const GemmArgs& P, int bxn, int bym) {
    extern __shared__ __half smh[];
    const unsigned sA_u = (unsigned)__cvta_generic_to_shared(smh);
    const unsigned sB_u = sA_u + (unsigned)(GSTAGES * GA_BUF) * 2u;

    const int tid  = threadIdx.x;
    const int bm   = bym * GBM;
    const int bn   = bxn * GBN;
    const int warp = tid >> 5, lane = tid & 31;
    const int wm = (warp & 1) << 6;
    const int wn = (warp >> 1) << 5;
    const int g  = lane >> 2, tg = lane & 3;

    const int t    = lane >> 3;
    const int a_m  = ((t & 1) << 3) + (lane & 7);
    const int a_ko = (t >> 1) << 3;
    const int b_n  = ((t >> 1) << 3) + (lane & 7);
    const int b_ko = (t & 1) << 3;

    float acc[4][4][4];
    #pragma unroll
    for (int mt = 0; mt < 4; ++mt)
        #pragma unroll
        for (int nt = 0; nt < 4; ++nt)
            #pragma unroll
            for (int i = 0; i < 4; ++i) acc[mt][nt][i] = 0.f;

    auto load_stage = [&](int kt, int buf) {
        const int k0 = kt * 64;
        unsigned sab = sA_u + (unsigned)(buf * GA_BUF) * 2u;
        #pragma unroll
        for (int it = 0; it < 4; ++it) {
            int idx = tid + it * 256;
            int row = idx >> 3, seg = idx & 7;
            cp16u(sab + (unsigned)(row * HS + seg * 8) * 2u,
                  P.A + (size_t)(bm + row) * P.lda + k0 + seg * 8);
        }
        unsigned sbb = sB_u + (unsigned)(buf * GB_BUF) * 2u;
        #pragma unroll
        for (int it = 0; it < 4; ++it) {
            int idx = tid + it * 256;
            int row = idx >> 3, seg = idx & 7;
            cp16u(sbb + (unsigned)(row * HS + seg * 8) * 2u,
                  P.Wt + (size_t)(bn + row) * P.ldw + k0 + seg * 8);
        }
        asm volatile("cp.async.commit_group;\n");
    };

    auto compute = [&](int buf) {
        const unsigned pA = sA_u + (unsigned)(buf * GA_BUF) * 2u;
        const unsigned pB = sB_u + (unsigned)(buf * GB_BUF) * 2u;
        #pragma unroll
        for (int kk = 0; kk < 4; ++kk) {
            unsigned af[4][4], bf[4][2];
            #pragma unroll
            for (int mt = 0; mt < 4; ++mt) {
                unsigned addr = pA + (unsigned)(((wm + (mt << 4) + a_m) * HS
                                                + (kk << 4) + a_ko) << 1);
                ldm4(af[mt][0], af[mt][1], af[mt][2], af[mt][3], addr);
            }
            #pragma unroll
            for (int p = 0; p < 2; ++p) {
                unsigned addr = pB + (unsigned)(((wn + (p << 4) + b_n) * HS
                                                + (kk << 4) + b_ko) << 1);
                ldm4(bf[2*p][0], bf[2*p][1], bf[2*p+1][0], bf[2*p+1][1], addr);
            }
            #pragma unroll
            for (int mt = 0; mt < 4; ++mt)
                #pragma unroll
                for (int nt = 0; nt < 4; ++nt)
                    mma_f16(acc[mt][nt], af[mt], bf[nt]);
        }
    };

    #pragma unroll
    for (int s = 0; s < GSTAGES - 1; ++s) load_stage(s, s);

    for (int kt = 0; kt < P.ktiles; ++kt) {
        asm volatile("cp.async.wait_group %0;\n" :: "n"(GSTAGES - 2));
        __syncthreads();
        int nxt = kt + GSTAGES - 1;
        if (nxt < P.ktiles) load_stage(nxt, nxt % GSTAGES);
        else asm volatile("cp.async.commit_group;\n");
        compute(kt % GSTAGES);
    }

    float ca0 = 0.f, ca1 = 0.f;
    if (P.avec) { ca0 = P.avec[0]; ca1 = P.avec[1]; }

    #pragma unroll
    for (int mt = 0; mt < 4; ++mt) {
        int r = bm + wm + (mt << 4);
        int m0 = r + g, m1 = r + g + 8;
        const float* q0 = P.Q ? P.Q + (size_t)(m0 / 11) * P.ldq : nullptr;
        const float* q1 = P.Q ? P.Q + (size_t)(m1 / 11) * P.ldq : nullptr;
        const float* t0 = P.T ? P.T + (size_t)P.seq[m0] * P.ldt : nullptr;
        const float* t1p = P.T ? P.T + (size_t)P.seq[m1] * P.ldt : nullptr;
        #pragma unroll
        for (int nt = 0; nt < 4; ++nt) {
            int c = bn + wn + (nt << 3) + (tg << 1);
            #pragma unroll
            for (int half = 0; half < 2; ++half) {
                int cc = c + half;
                if (cc >= P.Nzero) continue;
                float v0 = 0.f, v1 = 0.f;
                if (cc < P.Nout) {
                    float bb = P.bias ? P.bias[cc] : 0.f;
                    v0 = acc[mt][nt][half]     + bb;
                    v1 = acc[mt][nt][half + 2] + bb;
                    if (q0) { v0 += q0[cc]; v1 += q1[cc]; }
                    if (t0) { v0 += t0[cc]; v1 += t1p[cc]; }
                }
                if (P.avec) {
                    float p0 = P.Pg[(size_t)m0 * P.ldc + cc], n0v = P.NF[(size_t)m0 * P.ldc + cc];
                    float p1 = P.Pg[(size_t)m1 * P.ldc + cc], n1v = P.NF[(size_t)m1 * P.ldc + cc];
                    P.Cf[(size_t)m0 * P.ldc + cc] = sigmoidf_(p0) * n0v * ca0 + v0 * ca1;
                    P.Cf[(size_t)m1 * P.ldc + cc] = sigmoidf_(p1) * n1v * ca0 + v1 * ca1;
                } else if (P.Ch) {
                    P.Ch[(size_t)m0 * P.ldc + cc] = __float2half(fmaxf(v0, 0.f));
                    P.Ch[(size_t)m1 * P.ldc + cc] = __float2half(fmaxf(v1, 0.f));
                } else if (cc < P.Nout) {
                    P.Cf[(size_t)m0 * P.ldc + cc] = v0;
                    P.Cf[(size_t)m1 * P.ldc + cc] = v1;
                }
            }
        }
    }
}

__global__ __launch_bounds__(256, 2) void gemm_single(GemmArgs P) {
    gemm_body(P, blockIdx.x, blockIdx.y);
}
__global__ __launch_bounds__(256, 2) void gemm_dual(GemmArgs Pa, GemmArgs Pb, int na) {
    int i = blockIdx.x;
    if (i < na) gemm_body(Pa, i % Pa.gn, i / Pa.gn);
    else { i -= na; gemm_body(Pb, i % Pb.gn, i / Pb.gn); }
}
__global__ __launch_bounds__(256, 2) void gemm_quad(
    GemmArgs Pa, GemmArgs Pb, GemmArgs Pc, GemmArgs Pd, int na, int nb, int nc) {
    int i = blockIdx.x;
    if (i < na) { gemm_body(Pa, i % Pa.gn, i / Pa.gn); return; }
    i -= na;
    if (i < nb) { gemm_body(Pb, i % Pb.gn, i / Pb.gn); return; }
    i -= nb;
    if (i < nc) { gemm_body(Pc, i % Pc.gn, i / Pc.gn); return; }
    i -= nc;
    gemm_body(Pd, i % Pd.gn, i / Pd.gn);
}

__global__ __launch_bounds__(256) void final_kernel(
    const float* __restrict__ G1, const float* __restrict__ G2,
    const float* __restrict__ X2, const float* __restrict__ a2,
    float* __restrict__ out) {
    int b = blockIdx.x;
    float s0 = a2[0], s1 = a2[1];
    for (int i = threadIdx.x; i < D_SEQ_ / 4; i += blockDim.x) {
        float4 acc = make_float4(0.f, 0.f, 0.f, 0.f);
        for (int k = 0; k < K_; ++k) {
            size_t m = (size_t)b * K_ + k;
            float4 f1 = *(const float4*)(G1 + m * D_SEQ_ + i * 4);
            float4 f2 = *(const float4*)(G2 + m * D_SEQ_ + i * 4);
            float4 gn = *(const float4*)(X2 + m * D_SEQ_ + i * 4);
            acc.x += sigmoidf_(f1.x) * gn.x * s0 + f2.x * s1;
            acc.y += sigmoidf_(f1.y) * gn.y * s0 + f2.y * s1;
            acc.z += sigmoidf_(f1.z) * gn.z * s0 + f2.z * s1;
            acc.w += sigmoidf_(f1.w) * gn.w * s0 + f2.w * s1;
        }
        *(float4*)(out + (size_t)b * D_SEQ_ + i * 4) = acc;
    }
}

static GemmArgs mk(const __half* A, const __half* Wt, const float* bias,
                   float* Cf, __half* Ch, int lda, int ldw, int ktiles,
                   int Nout, int Nzero, int ldc,
                   const float* Q, int ldq, const float* T, int ldt, const int* seq,
                   const float* Pg, const float* NF, const float* avec, int gn) {
    GemmArgs p;
    p.A = A; p.Wt = Wt; p.bias = bias; p.Cf = Cf; p.Ch = Ch;
    p.lda = lda; p.ldw = ldw; p.ktiles = ktiles;
    p.Nout = Nout; p.Nzero = Nzero; p.ldc = ldc;
    p.Q = Q; p.ldq = ldq; p.T = T; p.ldt = ldt; p.seq = seq;
    p.Pg = Pg; p.NF = NF; p.avec = avec; p.gn = gn;
    return p;
}

extern "C" void kernel_launch(void* const* d_in, const int* in_sizes, int n_in,
                              void* d_out, int out_size) {
    const float* kin_in   = (const float*)d_in[0];
    const float* sub      = (const float*)d_in[1];
    const float* n2       = (const float*)d_in[2];
    const float* a        = (const float*)d_in[4];
    const float* a2       = (const float*)d_in[5];
    const float* phos     = (const float*)d_in[6];
    const float* g1_gamma = (const float*)d_in[7];
    const float* g1_beta  = (const float*)d_in[8];
    const float* g1_W     = (const float*)d_in[9];
    const float* g1_b     = (const float*)d_in[10];
    const float* r1_gamma = (const float*)d_in[11];
    const float* r1_beta  = (const float*)d_in[12];
    const float* r1_W1    = (const float*)d_in[13];
    const float* r1_b1    = (const float*)d_in[14];
    const float* r1_W2    = (const float*)d_in[15];
    const float* r1_b2    = (const float*)d_in[16];
    const float* g2_gamma = (const float*)d_in[17];
    const float* g2_beta  = (const float*)d_in[18];
    const float* g2_W     = (const float*)d_in[19];
    const float* g2_b     = (const float*)d_in[20];
    const float* r2_gamma = (const float*)d_in[21];
    const float* r2_beta  = (const float*)d_in[22];
    const float* r2_W1    = (const float*)d_in[23];
    const float* r2_b1    = (const float*)d_in[24];
    const float* r2_W2    = (const float*)d_in[25];
    const float* r2_b2    = (const float*)d_in[26];
    const int*   position = (const int*)d_in[27];
    const int*   raw_seq  = (const int*)d_in[28];

    float* out = (float*)d_out;
    float* graph_feature = out;
    float* node_feature  = out + (size_t)B_ * D_SEQ_;

    float *X, *P1, *P2, *kin, *Qg, *Qr, *Tg, *Tr, *psum, *psq, *psumK, *psqK, *ss;
    int* cnt;
    __half *Y, *XA, *XB, *KA, *KB, *Wt;
    cudaGetSymbolAddress((void**)&X,     g_X);
    cudaGetSymbolAddress((void**)&Y,     g_Y);
    cudaGetSymbolAddress((void**)&XA,    g_XA);
    cudaGetSymbolAddress((void**)&XB,    g_XB);
    cudaGetSymbolAddress((void**)&KA,    g_KA);
    cudaGetSymbolAddress((void**)&KB,    g_KB);
    cudaGetSymbolAddress((void**)&P1,    g_P1);
    cudaGetSymbolAddress((void**)&P2,    g_P2);
    cudaGetSymbolAddress((void**)&Wt,    g_Wt);
    cudaGetSymbolAddress((void**)&kin,   g_kin);
    cudaGetSymbolAddress((void**)&Qg,    g_Qg);
    cudaGetSymbolAddress((void**)&Qr,    g_Qr);
    cudaGetSymbolAddress((void**)&Tg,    g_Tg);
    cudaGetSymbolAddress((void**)&Tr,    g_Tr);
    cudaGetSymbolAddress((void**)&cnt,   g_cnt);
    cudaGetSymbolAddress((void**)&psum,  g_psum);
    cudaGetSymbolAddress((void**)&psq,   g_psq);
    cudaGetSymbolAddress((void**)&psumK, g_psumK);
    cudaGetSymbolAddress((void**)&psqK,  g_psqK);
    cudaGetSymbolAddress((void**)&ss,    g_ss);

    cudaFuncSetAttribute(gemm_single, cudaFuncAttributeMaxDynamicSharedMemorySize, GSMEM_BYTES);
    cudaFuncSetAttribute(gemm_dual,   cudaFuncAttributeMaxDynamicSharedMemorySize, GSMEM_BYTES);
    cudaFuncSetAttribute(gemm_quad,   cudaFuncAttributeMaxDynamicSharedMemorySize, GSMEM_BYTES);

    __half* Wt_g1  = Wt;
    __half* Wt_r11 = Wt_g1  + (size_t)1280 * KP1;
    __half* Wt_r12 = Wt_r11 + (size_t)1792 * KP1;
    __half* Wt_g2  = Wt_r12 + (size_t)1280 * KP1;
    __half* Wt_r21 = Wt_g2  + (size_t)1280 * KP2;
    __half* Wt_r22 = Wt_r21 + (size_t)NP_R21 * KP2;

    prep_kernel<<<NB_BUILD + 21392, 256>>>(
        g1_W, r1_W1, r1_W2, g2_W, r2_W1, r2_W2,
        Wt_g1, Wt_r11, Wt_r12, Wt_g2, Wt_r21, Wt_r22,
        kin_in, sub, n2, phos, position, kin, X, node_feature);

    stats1_kernel<<<329, 256>>>(X, node_feature, phos, kin, raw_seq,
                                psum, psq, psumK, psqK, cnt);
    finalize_all1<<<(EMB_ + 1284 + 255) / 256, 256>>>(psum, psq, psumK, psqK, cnt,
        g1_gamma, g1_beta, r1_gamma, r1_beta, g2_gamma, g2_beta, r2_gamma, r2_beta, ss);
    bn1_kernel<<<dim3(4, M_ + B_ + (NPROPS + 1023) / 1024), 256>>>(
        X, node_feature, phos, kin, ss, g2_W, r2_W1, Tg, Tr);

    // quad: r11 + g1 + Qr + Qg
    {
        GemmArgs pr11 = mk(XB, Wt_r11, r1_b1, nullptr, Y, KP1, KP1, 28, 1792, 1792, KP1,
                           nullptr, 0, nullptr, 0, nullptr, nullptr, nullptr, nullptr, 14);
        GemmArgs pg1  = mk(XA, Wt_g1,  g1_b,  P1, nullptr, KP1, KP1, 28, 1280, 1280, 1280,
                           nullptr, 0, nullptr, 0, nullptr, nullptr, nullptr, nullptr, 10);
        GemmArgs pqr  = mk(KB, Wt_r21 + 1280, nullptr, Qr, nullptr, D_SEQ_, KP2, 20,
                           EMB2_, EMB2_, EMB2_, nullptr, 0, nullptr, 0, nullptr,
                           nullptr, nullptr, nullptr, 21);
        GemmArgs pqg  = mk(KA, Wt_g2 + 1280, nullptr, Qg, nullptr, D_SEQ_, KP2, 20,
                           1280, 1280, 1280, nullptr, 0, nullptr, 0, nullptr,
                           nullptr, nullptr, nullptr, 10);
        gemm_quad<<<1232 + 880 + 168 + 80, 256, GSMEM_BYTES>>>(
            pr11, pg1, pqr, pqg, 1232, 880, 168);
    }
    // r12 with fused combine -> X2 (ld 1280, overwrites g_X)
    {
        GemmArgs pr12 = mk(Y, Wt_r12, r1_b2, X, nullptr, KP1, KP1, 28, 1280, 1280, 1280,
                           nullptr, 0, nullptr, 0, nullptr, P1, node_feature, a, 10);
        gemm_single<<<dim3(10, 88), 256, GSMEM_BYTES>>>(pr12);
    }

    stats2_kernel<<<220, 256>>>(X, psum, psq);
    finalize2_kernel<<<5, 256>>>(psum, psq, g2_gamma, g2_beta, r2_gamma, r2_beta, ss);
    bn2x_kernel<<<dim3(3, M_), 256>>>(X, ss);

    {
        GemmArgs pr21 = mk(XB, Wt_r21, r2_b1, nullptr, Y, D_SEQ_, KP2, 20, EMB2_, KP2, KP2,
                           Qr, EMB2_, Tr, EMB2_, raw_seq, nullptr, nullptr, nullptr, 21);
        GemmArgs pg2  = mk(XA, Wt_g2,  g2_b,  P1, nullptr, D_SEQ_, KP2, 20, 1280, 1280, 1280,
                           Qg, 1280, Tg, 1280, raw_seq, nullptr, nullptr, nullptr, 10);
        gemm_dual<<<21 * 88 + 10 * 88, 256, GSMEM_BYTES>>>(pr21, pg2, 21 * 88);
    }
    {
        GemmArgs pr22 = mk(Y, Wt_r22, r2_b2, P2, nullptr, KP2, KP2, 41, 1280, 1280, 1280,
                           nullptr, 0, nullptr, 0, nullptr, nullptr, nullptr, nullptr, 10);
        gemm_single<<<dim3(10, 88), 256, GSMEM_BYTES>>>(pr22);
    }

    final_kernel<<<B_, 256>>>(P1, P2, X, a2, graph_feature);
}